// round 1
// baseline (speedup 1.0000x reference)
#include <cuda_runtime.h>
#include <math.h>

// Problem constants
#define BDIM 8
#define NDIM 1024
#define DDIM 256
#define HDIM 8
#define FDIM 128
#define MDIM (BDIM * NDIM)   // 8192

#define ALPHA 0.2f

// ---------------- scratch (device globals; no allocs allowed) ----------------
__device__ float g_h1[HDIM * MDIM * FDIM];      // [h][b*N+n][f]   33.5 MB
__device__ float g_xc[MDIM * HDIM * FDIM];      // [b*N+n][h*F+f]  33.5 MB
__device__ float g_h2[MDIM * FDIM];             // [b*N+n][f]
__device__ float g_f1a[HDIM * MDIM];
__device__ float g_f2a[HDIM * MDIM];
__device__ float g_f1b[MDIM];
__device__ float g_f2b[MDIM];
__device__ float g_f2maxa[HDIM * BDIM];
__device__ float g_f2maxb[BDIM];

__device__ __forceinline__ float lrelu(float x) { return x > 0.f ? x : ALPHA * x; }
__device__ __forceinline__ float elu1(float x)  { return x > 0.f ? x : expm1f(x); }

// ---------------- generic tiled SGEMM: O[r][f] = sum_k A[r][k] * W[k][f] ----
// BM=64 rows, BN=128 cols (full F), BK=32. 256 threads, 8x4 micro-tile.
// blockIdx.y = head; W and O offset per head.
__global__ void gemm_kernel(const float* __restrict__ A, int lda,
                            const float* __restrict__ Wbase, int wHeadStride,
                            int K,
                            float* __restrict__ Obase, int oHeadStride)
{
    const int h  = blockIdx.y;
    const float* W = Wbase + (size_t)h * wHeadStride;
    float*       O = Obase + (size_t)h * oHeadStride;
    const int r0 = blockIdx.x * 64;

    __shared__ float As[32][65];                  // [k][i], padded
    __shared__ __align__(16) float Bs[32][128];   // [k][f]

    const int tid = threadIdx.x;
    const int tx = tid & 31;   // col group (32 groups x 4 cols)
    const int ty = tid >> 5;   // row group (8 groups x 8 rows)

    float acc[8][4];
#pragma unroll
    for (int u = 0; u < 8; u++)
#pragma unroll
        for (int v = 0; v < 4; v++) acc[u][v] = 0.f;

    for (int k0 = 0; k0 < K; k0 += 32) {
#pragma unroll
        for (int l = 0; l < 8; l++) {
            int idx = tid + l * 256;
            int i = idx >> 5, k = idx & 31;
            As[k][i] = A[(size_t)(r0 + i) * lda + k0 + k];
        }
#pragma unroll
        for (int l = 0; l < 16; l++) {
            int idx = tid + l * 256;
            int kk = idx >> 7, f = idx & 127;
            Bs[kk][f] = W[(size_t)(k0 + kk) * FDIM + f];
        }
        __syncthreads();
#pragma unroll
        for (int k = 0; k < 32; k++) {
            float av[8];
#pragma unroll
            for (int u = 0; u < 8; u++) av[u] = As[k][ty * 8 + u];
            float4 bv = *(const float4*)&Bs[k][tx * 4];
#pragma unroll
            for (int u = 0; u < 8; u++) {
                acc[u][0] += av[u] * bv.x;
                acc[u][1] += av[u] * bv.y;
                acc[u][2] += av[u] * bv.z;
                acc[u][3] += av[u] * bv.w;
            }
        }
        __syncthreads();
    }
#pragma unroll
    for (int u = 0; u < 8; u++) {
        int r = r0 + ty * 8 + u;
        float4 v = make_float4(acc[u][0], acc[u][1], acc[u][2], acc[u][3]);
        *(float4*)&O[(size_t)r * FDIM + tx * 4] = v;
    }
}

// ---------------- f1/f2: per row of Hmat, f1=h.a1, f2=h.a2 ------------------
// one warp per row; Hmat rows are contiguous [rowGlobal][F]; head = row / rowsPerHead.
__global__ void f1f2_kernel(const float* __restrict__ Hmat,
                            const float* __restrict__ Abase, int aHeadStride,
                            float* __restrict__ f1, float* __restrict__ f2,
                            int rowsPerHead)
{
    int warp = (blockIdx.x * blockDim.x + threadIdx.x) >> 5;
    int lane = threadIdx.x & 31;
    int h = warp / rowsPerHead;
    const float* a = Abase + (size_t)h * aHeadStride;
    const float* hr = Hmat + (size_t)warp * FDIM;
    float s1 = 0.f, s2 = 0.f;
#pragma unroll
    for (int u = 0; u < 4; u++) {
        int c = lane + 32 * u;
        float v = hr[c];
        s1 += v * a[c];
        s2 += v * a[FDIM + c];
    }
#pragma unroll
    for (int off = 16; off; off >>= 1) {
        s1 += __shfl_xor_sync(0xffffffffu, s1, off);
        s2 += __shfl_xor_sync(0xffffffffu, s2, off);
    }
    if (lane == 0) { f1[warp] = s1; f2[warp] = s2; }
}

// ---------------- per-(h,b) max over f2 --------------------------------------
__global__ void f2max_kernel(const float* __restrict__ f2, float* __restrict__ out, int n)
{
    __shared__ float red[256];
    const float* p = f2 + (size_t)blockIdx.x * n;
    float m = -INFINITY;
    for (int i = threadIdx.x; i < n; i += 256) m = fmaxf(m, p[i]);
    red[threadIdx.x] = m;
    __syncthreads();
    for (int s = 128; s; s >>= 1) {
        if (threadIdx.x < s) red[threadIdx.x] = fmaxf(red[threadIdx.x], red[threadIdx.x + s]);
        __syncthreads();
    }
    if (threadIdx.x == 0) out[blockIdx.x] = red[0];
}

// ---------------- fused attention: softmax(lrelu(f1_i+f2_j)) @ V, + elu -----
// BM=64 rows (i), BN=128 (all F), BK=32 (j tile). No online rescale: row max is
// m_i = lrelu(f1_i + max_j f2_j), exact because lrelu is monotone.
// out[(b*N + i) * outRowStride + h*headColMul + f]; elu applied nElu times.
__global__ void attn_kernel(const float* __restrict__ V,
                            const float* __restrict__ f1,
                            const float* __restrict__ f2,
                            const float* __restrict__ f2max,
                            float* __restrict__ out,
                            int Bdim, int outRowStride, int headColMul, int nElu)
{
    const int hb = blockIdx.z;
    const int h = hb / Bdim, b = hb % Bdim;
    const int i0 = blockIdx.x * 64;
    const float* Vp  = V  + (size_t)hb * NDIM * FDIM;
    const float* f1p = f1 + (size_t)hb * NDIM;
    const float* f2p = f2 + (size_t)hb * NDIM;

    __shared__ float Ws[32][65];                 // [jloc][i]
    __shared__ __align__(16) float Vs[32][128];  // [jloc][f]
    __shared__ float f1s[64], ms[64], dsh[64];

    const int tid = threadIdx.x;
    const int tx = tid & 31, ty = tid >> 5;

    if (tid < 64) {
        float v = f1p[i0 + tid];
        f1s[tid] = v;
        ms[tid] = lrelu(v + f2max[hb]);
    }
    __syncthreads();

    float acc[8][4];
#pragma unroll
    for (int u = 0; u < 8; u++)
#pragma unroll
        for (int v = 0; v < 4; v++) acc[u][v] = 0.f;
    float dsum = 0.f;

    for (int j0 = 0; j0 < NDIM; j0 += 32) {
        // compute W tile: each thread owns fixed jloc = tx across 8 rows
        float f2v = f2p[j0 + tx];
#pragma unroll
        for (int l = 0; l < 8; l++) {
            int i = ty + l * 8;
            float s = lrelu(f1s[i] + f2v);
            Ws[tx][i] = __expf(s - ms[i]);
        }
        // load V tile
#pragma unroll
        for (int l = 0; l < 16; l++) {
            int idx = tid + l * 256;
            int jj = idx >> 7, f = idx & 127;
            Vs[jj][f] = Vp[(size_t)(j0 + jj) * FDIM + f];
        }
        __syncthreads();

        // denominator accumulation (threads 0..63 own one row each)
        if (tid < 64) {
            float d = 0.f;
#pragma unroll
            for (int k = 0; k < 32; k++) d += Ws[k][tid];
            dsum += d;
        }
        // P @ V micro-GEMM
#pragma unroll
        for (int k = 0; k < 32; k++) {
            float av[8];
#pragma unroll
            for (int u = 0; u < 8; u++) av[u] = Ws[k][ty * 8 + u];
            float4 bv = *(const float4*)&Vs[k][tx * 4];
#pragma unroll
            for (int u = 0; u < 8; u++) {
                acc[u][0] += av[u] * bv.x;
                acc[u][1] += av[u] * bv.y;
                acc[u][2] += av[u] * bv.z;
                acc[u][3] += av[u] * bv.w;
            }
        }
        __syncthreads();
    }

    if (tid < 64) dsh[tid] = dsum;
    __syncthreads();

#pragma unroll
    for (int u = 0; u < 8; u++) {
        int i = ty * 8 + u;
        float inv = 1.f / dsh[i];
        float4 v;
        v.x = elu1(acc[u][0] * inv);
        v.y = elu1(acc[u][1] * inv);
        v.z = elu1(acc[u][2] * inv);
        v.w = elu1(acc[u][3] * inv);
        if (nElu == 2) { v.x = elu1(v.x); v.y = elu1(v.y); v.z = elu1(v.z); v.w = elu1(v.w); }
        size_t oidx = (size_t)(b * NDIM + i0 + i) * outRowStride + h * headColMul + tx * 4;
        *(float4*)&out[oidx] = v;
    }
}

// -----------------------------------------------------------------------------
extern "C" void kernel_launch(void* const* d_in, const int* in_sizes, int n_in,
                              void* d_out, int out_size)
{
    const float* x       = (const float*)d_in[0];
    // d_in[1] = adj : discarded by the reference math
    const float* W_heads = (const float*)d_in[2];
    const float* a_heads = (const float*)d_in[3];
    const float* W_out   = (const float*)d_in[4];
    const float* a_out   = (const float*)d_in[5];
    float* out = (float*)d_out;

    float *h1, *xc, *h2, *f1a, *f2a, *f1b, *f2b, *f2ma, *f2mb;
    cudaGetSymbolAddress((void**)&h1,   g_h1);
    cudaGetSymbolAddress((void**)&xc,   g_xc);
    cudaGetSymbolAddress((void**)&h2,   g_h2);
    cudaGetSymbolAddress((void**)&f1a,  g_f1a);
    cudaGetSymbolAddress((void**)&f2a,  g_f2a);
    cudaGetSymbolAddress((void**)&f1b,  g_f1b);
    cudaGetSymbolAddress((void**)&f2b,  g_f2b);
    cudaGetSymbolAddress((void**)&f2ma, g_f2maxa);
    cudaGetSymbolAddress((void**)&f2mb, g_f2maxb);

    // ---- layer 1: h1[h] = x @ W_heads[h] ----
    gemm_kernel<<<dim3(MDIM / 64, HDIM), 256>>>(x, DDIM, W_heads, DDIM * FDIM, DDIM,
                                                h1, MDIM * FDIM);
    // f1/f2 per (h, row)
    f1f2_kernel<<<(HDIM * MDIM) / 8, 256>>>(h1, a_heads, 2 * FDIM, f1a, f2a, MDIM);
    // max_j f2 per (h,b)
    f2max_kernel<<<HDIM * BDIM, 256>>>(f2a, f2ma, NDIM);
    // attention + elu, scatter to xc[b][n][h*F+f]
    attn_kernel<<<dim3(NDIM / 64, 1, HDIM * BDIM), 256>>>(h1, f1a, f2a, f2ma, xc,
                                                          BDIM, HDIM * FDIM, FDIM, 1);

    // ---- layer 2: h2 = xc @ W_out ----
    gemm_kernel<<<dim3(MDIM / 64, 1), 256>>>(xc, HDIM * FDIM, W_out, 0, HDIM * FDIM,
                                             h2, 0);
    f1f2_kernel<<<MDIM / 8, 256>>>(h2, a_out, 0, f1b, f2b, MDIM);
    f2max_kernel<<<BDIM, 256>>>(f2b, f2mb, NDIM);
    // attention + double elu, write final output (B,N,F)
    attn_kernel<<<dim3(NDIM / 64, 1, BDIM), 256>>>(h2, f1b, f2b, f2mb, out,
                                                   BDIM, FDIM, 0, 2);
}

// round 2
// speedup vs baseline: 1.1256x; 1.1256x over previous
#include <cuda_runtime.h>
#include <math.h>

#define BDIM 8
#define NDIM 1024
#define DDIM 256
#define HDIM 8
#define FDIM 128
#define MDIM (BDIM * NDIM)   // 8192
#define ALPHA 0.2f

// ---------------- scratch (device globals) ----------------
__device__ float g_h1[HDIM * MDIM * FDIM];      // 33.5 MB
__device__ float g_xc[MDIM * HDIM * FDIM];      // 33.5 MB
__device__ float g_h2[MDIM * FDIM];             // 4 MB
__device__ float g_f1a[HDIM * MDIM];
__device__ float g_f2a[HDIM * MDIM];
__device__ float g_f1b[MDIM];
__device__ float g_f2b[MDIM];
__device__ float g_f2s[64 * 1024];              // sorted f2
__device__ int   g_perm[64 * 1024];
__device__ float g_vv[64 * 1024];               // e^{f2-M} sorted order
__device__ float g_zz[64 * 1024];               // e^{0.2(f2-M)}
__device__ float g_suf[64 * 1025 * FDIM];       // pos suffix sums, 33.6 MB
__device__ float g_pre[64 * 1025 * FDIM];       // neg prefix sums, 33.6 MB
__device__ float g_sufv[64 * 1025];
__device__ float g_prez[64 * 1025];
__device__ float g_mf2[64];

__device__ __forceinline__ float lrelu(float x) { return x > 0.f ? x : ALPHA * x; }
__device__ __forceinline__ float elu1(float x)  { return x > 0.f ? x : expm1f(x); }

// ---------------- tiled SGEMM: O[r][f] = sum_k A[r][k] * W[k][f] ------------
__global__ void gemm_kernel(const float* __restrict__ A, int lda,
                            const float* __restrict__ Wbase, int wHeadStride,
                            int K,
                            float* __restrict__ Obase, int oHeadStride)
{
    const int h  = blockIdx.y;
    const float* W = Wbase + (size_t)h * wHeadStride;
    float*       O = Obase + (size_t)h * oHeadStride;
    const int r0 = blockIdx.x * 64;

    __shared__ float As[32][65];
    __shared__ __align__(16) float Bs[32][128];

    const int tid = threadIdx.x;
    const int tx = tid & 31;
    const int ty = tid >> 5;

    float acc[8][4];
#pragma unroll
    for (int u = 0; u < 8; u++)
#pragma unroll
        for (int v = 0; v < 4; v++) acc[u][v] = 0.f;

    for (int k0 = 0; k0 < K; k0 += 32) {
#pragma unroll
        for (int l = 0; l < 8; l++) {
            int idx = tid + l * 256;
            int i = idx >> 5, k = idx & 31;
            As[k][i] = A[(size_t)(r0 + i) * lda + k0 + k];
        }
#pragma unroll
        for (int l = 0; l < 16; l++) {
            int idx = tid + l * 256;
            int kk = idx >> 7, f = idx & 127;
            Bs[kk][f] = W[(size_t)(k0 + kk) * FDIM + f];
        }
        __syncthreads();
#pragma unroll
        for (int k = 0; k < 32; k++) {
            float av[8];
#pragma unroll
            for (int u = 0; u < 8; u++) av[u] = As[k][ty * 8 + u];
            float4 bv = *(const float4*)&Bs[k][tx * 4];
#pragma unroll
            for (int u = 0; u < 8; u++) {
                acc[u][0] += av[u] * bv.x;
                acc[u][1] += av[u] * bv.y;
                acc[u][2] += av[u] * bv.z;
                acc[u][3] += av[u] * bv.w;
            }
        }
        __syncthreads();
    }
#pragma unroll
    for (int u = 0; u < 8; u++) {
        int r = r0 + ty * 8 + u;
        float4 v = make_float4(acc[u][0], acc[u][1], acc[u][2], acc[u][3]);
        *(float4*)&O[(size_t)r * FDIM + tx * 4] = v;
    }
}

// ---------------- f1/f2 per row ------------------
__global__ void f1f2_kernel(const float* __restrict__ Hmat,
                            const float* __restrict__ Abase, int aHeadStride,
                            float* __restrict__ f1, float* __restrict__ f2,
                            int rowsPerHead)
{
    int warp = (blockIdx.x * blockDim.x + threadIdx.x) >> 5;
    int lane = threadIdx.x & 31;
    int h = warp / rowsPerHead;
    const float* a = Abase + (size_t)h * aHeadStride;
    const float* hr = Hmat + (size_t)warp * FDIM;
    float s1 = 0.f, s2 = 0.f;
#pragma unroll
    for (int u = 0; u < 4; u++) {
        int c = lane + 32 * u;
        float v = hr[c];
        s1 += v * a[c];
        s2 += v * a[FDIM + c];
    }
#pragma unroll
    for (int off = 16; off; off >>= 1) {
        s1 += __shfl_xor_sync(0xffffffffu, s1, off);
        s2 += __shfl_xor_sync(0xffffffffu, s2, off);
    }
    if (lane == 0) { f1[warp] = s1; f2[warp] = s2; }
}

// ---------------- sort f2 per (h,b) + weight arrays + scalar scans ----------
// 512 threads, 1024-element bitonic sort in smem; then Hillis-Steele scans of
// z (prefix) and v (suffix) for the softmax denominators.
__global__ void sort_kernel(const float* __restrict__ f2,
                            float* __restrict__ f2s, int* __restrict__ perm,
                            float* __restrict__ vv, float* __restrict__ zz,
                            float* __restrict__ sufv, float* __restrict__ prez,
                            float* __restrict__ mf2out)
{
    __shared__ float val[1024];
    __shared__ int   idx[1024];
    __shared__ float sA[1024];
    __shared__ float sB[1024];
    const int hb = blockIdx.x;
    const int tid = threadIdx.x;

    for (int t = tid; t < 1024; t += 512) { val[t] = f2[hb * 1024 + t]; idx[t] = t; }
    __syncthreads();

    for (int k = 2; k <= 1024; k <<= 1) {
        for (int j = k >> 1; j > 0; j >>= 1) {
            for (int t = tid; t < 1024; t += 512) {
                int t2 = t ^ j;
                if (t2 > t) {
                    bool up = ((t & k) == 0);
                    float a = val[t], b = val[t2];
                    if ((a > b) == up) {
                        val[t] = b; val[t2] = a;
                        int ti = idx[t]; idx[t] = idx[t2]; idx[t2] = ti;
                    }
                }
            }
            __syncthreads();
        }
    }

    const float M = val[1023];
    for (int t = tid; t < 1024; t += 512) {
        float fv = val[t];
        f2s[hb * 1024 + t]  = fv;
        perm[hb * 1024 + t] = idx[t];
        float v = __expf(fv - M);
        float z = __expf(0.2f * (fv - M));
        vv[hb * 1024 + t] = v;
        zz[hb * 1024 + t] = z;
        sA[t] = z;
    }
    __syncthreads();

    // inclusive prefix scan of z
    {
        float* src = sA; float* dst = sB;
        for (int off = 1; off < 1024; off <<= 1) {
            for (int t = tid; t < 1024; t += 512)
                dst[t] = src[t] + (t >= off ? src[t - off] : 0.f);
            __syncthreads();
            float* tmp = src; src = dst; dst = tmp;
        }
        for (int t = tid; t < 1024; t += 512)
            prez[hb * 1025 + t + 1] = src[t];
        if (tid == 0) { prez[hb * 1025] = 0.f; mf2out[hb] = M; }
    }
    __syncthreads();

    // inclusive suffix scan of v (scan of reversed array)
    for (int t = tid; t < 1024; t += 512) sA[t] = vv[hb * 1024 + 1023 - t];
    __syncthreads();
    {
        float* src = sA; float* dst = sB;
        for (int off = 1; off < 1024; off <<= 1) {
            for (int t = tid; t < 1024; t += 512)
                dst[t] = src[t] + (t >= off ? src[t - off] : 0.f);
            __syncthreads();
            float* tmp = src; src = dst; dst = tmp;
        }
        for (int t = tid; t < 1024; t += 512)
            sufv[hb * 1025 + 1023 - t] = src[t];
        if (tid == 0) sufv[hb * 1025 + 1024] = 0.f;
    }
}

// ---------------- streaming scans of weighted V along sorted order ----------
// thread t owns column f=t; coalesced 512B row reads in permuted order.
__global__ void scan_kernel(const float* __restrict__ V,
                            const int* __restrict__ perm,
                            const float* __restrict__ vv,
                            const float* __restrict__ zz,
                            float* __restrict__ suf, float* __restrict__ pre)
{
    __shared__ int   perm_s[1024];
    __shared__ float v_s[1024];
    __shared__ float z_s[1024];
    const int hb = blockIdx.x;
    const int t = threadIdx.x;   // 128 threads

    for (int r = t; r < 1024; r += 128) {
        perm_s[r] = perm[hb * 1024 + r];
        v_s[r]    = vv[hb * 1024 + r];
        z_s[r]    = zz[hb * 1024 + r];
    }
    __syncthreads();

    const float* Vh = V + (size_t)hb * NDIM * FDIM;
    const size_t base = (size_t)hb * 1025 * FDIM;

    // neg prefix (ascending)
    float acc = 0.f;
    pre[base + t] = 0.f;
#pragma unroll 4
    for (int r = 0; r < 1024; r++) {
        float x = Vh[(size_t)perm_s[r] * FDIM + t];
        acc += z_s[r] * x;
        pre[base + (size_t)(r + 1) * FDIM + t] = acc;
    }
    // pos suffix (descending)
    acc = 0.f;
    suf[base + (size_t)1024 * FDIM + t] = 0.f;
#pragma unroll 4
    for (int r = 1023; r >= 0; r--) {
        float x = Vh[(size_t)perm_s[r] * FDIM + t];
        acc += v_s[r] * x;
        suf[base + (size_t)r * FDIM + t] = acc;
    }
}

// ---------------- output: binary search threshold + combine + elu -----------
__global__ void out_kernel(const float* __restrict__ f1,
                           const float* __restrict__ f2s,
                           const float* __restrict__ mf2,
                           const float* __restrict__ suf,
                           const float* __restrict__ pre,
                           const float* __restrict__ sufv,
                           const float* __restrict__ prez,
                           float* __restrict__ out,
                           int Bdim, int outRowStride, int headColMul, int nElu)
{
    __shared__ float s_f2[1024];
    const int hb = blockIdx.z;
    const int h = hb / Bdim, b = hb % Bdim;
    for (int r = threadIdx.x; r < 1024; r += 256) s_f2[r] = f2s[hb * 1024 + r];
    __syncthreads();

    const int warp = threadIdx.x >> 5, lane = threadIdx.x & 31;
    const int i = blockIdx.x * 8 + warp;

    float f1v = f1[(size_t)hb * NDIM + i];
    float su = f1v + mf2[hb];
    float m = lrelu(su);
    float u = __expf(su - m);
    float w = __expf(0.2f * su - m);
    float target = -f1v;

    int lo = 0, hi = 1024;
    while (lo < hi) {
        int mid = (lo + hi) >> 1;
        if (s_f2[mid] <= target) lo = mid + 1; else hi = mid;
    }
    const int tt = lo;

    float d = u * sufv[hb * 1025 + tt] + w * prez[hb * 1025 + tt];
    float inv = 1.f / d;

    const size_t rowbase = ((size_t)hb * 1025 + tt) * FDIM + lane * 4;
    float4 sv = *(const float4*)&suf[rowbase];
    float4 pv = *(const float4*)&pre[rowbase];
    float4 o;
    o.x = elu1((u * sv.x + w * pv.x) * inv);
    o.y = elu1((u * sv.y + w * pv.y) * inv);
    o.z = elu1((u * sv.z + w * pv.z) * inv);
    o.w = elu1((u * sv.w + w * pv.w) * inv);
    if (nElu == 2) { o.x = elu1(o.x); o.y = elu1(o.y); o.z = elu1(o.z); o.w = elu1(o.w); }

    size_t oidx = ((size_t)(b * NDIM + i)) * outRowStride + h * headColMul + lane * 4;
    *(float4*)&out[oidx] = o;
}

// -----------------------------------------------------------------------------
extern "C" void kernel_launch(void* const* d_in, const int* in_sizes, int n_in,
                              void* d_out, int out_size)
{
    const float* x       = (const float*)d_in[0];
    // d_in[1] = adj : discarded by the reference math
    const float* W_heads = (const float*)d_in[2];
    const float* a_heads = (const float*)d_in[3];
    const float* W_out   = (const float*)d_in[4];
    const float* a_out   = (const float*)d_in[5];
    float* out = (float*)d_out;

    float *h1, *xc, *h2, *f1a, *f2a, *f1b, *f2b;
    float *f2s, *vv, *zz, *suf, *pre, *sufv, *prez, *mf2;
    int *perm;
    cudaGetSymbolAddress((void**)&h1,   g_h1);
    cudaGetSymbolAddress((void**)&xc,   g_xc);
    cudaGetSymbolAddress((void**)&h2,   g_h2);
    cudaGetSymbolAddress((void**)&f1a,  g_f1a);
    cudaGetSymbolAddress((void**)&f2a,  g_f2a);
    cudaGetSymbolAddress((void**)&f1b,  g_f1b);
    cudaGetSymbolAddress((void**)&f2b,  g_f2b);
    cudaGetSymbolAddress((void**)&f2s,  g_f2s);
    cudaGetSymbolAddress((void**)&perm, g_perm);
    cudaGetSymbolAddress((void**)&vv,   g_vv);
    cudaGetSymbolAddress((void**)&zz,   g_zz);
    cudaGetSymbolAddress((void**)&suf,  g_suf);
    cudaGetSymbolAddress((void**)&pre,  g_pre);
    cudaGetSymbolAddress((void**)&sufv, g_sufv);
    cudaGetSymbolAddress((void**)&prez, g_prez);
    cudaGetSymbolAddress((void**)&mf2,  g_mf2);

    // ---- layer 1 ----
    gemm_kernel<<<dim3(MDIM / 64, HDIM), 256>>>(x, DDIM, W_heads, DDIM * FDIM, DDIM,
                                                h1, MDIM * FDIM);
    f1f2_kernel<<<(HDIM * MDIM) / 8, 256>>>(h1, a_heads, 2 * FDIM, f1a, f2a, MDIM);
    sort_kernel<<<HDIM * BDIM, 512>>>(f2a, f2s, perm, vv, zz, sufv, prez, mf2);
    scan_kernel<<<HDIM * BDIM, 128>>>(h1, perm, vv, zz, suf, pre);
    out_kernel<<<dim3(NDIM / 8, 1, HDIM * BDIM), 256>>>(f1a, f2s, mf2, suf, pre,
                                                        sufv, prez, xc,
                                                        BDIM, HDIM * FDIM, FDIM, 1);

    // ---- layer 2 ----
    gemm_kernel<<<dim3(MDIM / 64, 1), 256>>>(xc, HDIM * FDIM, W_out, 0, HDIM * FDIM,
                                             h2, 0);
    f1f2_kernel<<<MDIM / 8, 256>>>(h2, a_out, 0, f1b, f2b, MDIM);
    sort_kernel<<<BDIM, 512>>>(f2b, f2s, perm, vv, zz, sufv, prez, mf2);
    scan_kernel<<<BDIM, 128>>>(h2, perm, vv, zz, suf, pre);
    out_kernel<<<dim3(NDIM / 8, 1, BDIM), 256>>>(f1b, f2s, mf2, suf, pre,
                                                 sufv, prez, out,
                                                 BDIM, FDIM, 0, 2);
}

// round 3
// speedup vs baseline: 1.1369x; 1.0100x over previous
#include <cuda_runtime.h>
#include <math.h>

#define BDIM 8
#define NDIM 1024
#define DDIM 256
#define HDIM 8
#define FDIM 128
#define MDIM (BDIM * NDIM)   // 8192
#define ALPHA 0.2f

// ---------------- scratch (device globals) ----------------
__device__ float g_h1[HDIM * MDIM * FDIM];      // 33.5 MB
__device__ float g_xc[MDIM * HDIM * FDIM];      // 33.5 MB
__device__ float g_h2[MDIM * FDIM];             // 4 MB
__device__ float g_f1a[HDIM * MDIM];
__device__ float g_f2a[HDIM * MDIM];
__device__ float g_f1b[MDIM];
__device__ float g_f2b[MDIM];
__device__ float g_f2s[64 * 1024];              // sorted f2
__device__ int   g_perm[64 * 1024];
__device__ float g_vv[64 * 1024];               // e^{f2-M} sorted order
__device__ float g_zz[64 * 1024];               // e^{0.2(f2-M)}
__device__ float g_sufv[64 * 1025];
__device__ float g_prez[64 * 1025];
__device__ float g_mf2[64];

__device__ __forceinline__ float lrelu(float x) { return x > 0.f ? x : ALPHA * x; }
__device__ __forceinline__ float elu1(float x)  { return x > 0.f ? x : expm1f(x); }

// ---------------- tiled SGEMM: O[r][f] = sum_k A[r][k] * W[k][f] ------------
__global__ void gemm_kernel(const float* __restrict__ A, int lda,
                            const float* __restrict__ Wbase, int wHeadStride,
                            int K,
                            float* __restrict__ Obase, int oHeadStride)
{
    const int h  = blockIdx.y;
    const float* W = Wbase + (size_t)h * wHeadStride;
    float*       O = Obase + (size_t)h * oHeadStride;
    const int r0 = blockIdx.x * 64;

    __shared__ float As[32][65];
    __shared__ __align__(16) float Bs[32][128];

    const int tid = threadIdx.x;
    const int tx = tid & 31;
    const int ty = tid >> 5;

    float acc[8][4];
#pragma unroll
    for (int u = 0; u < 8; u++)
#pragma unroll
        for (int v = 0; v < 4; v++) acc[u][v] = 0.f;

    for (int k0 = 0; k0 < K; k0 += 32) {
#pragma unroll
        for (int l = 0; l < 8; l++) {
            int idx = tid + l * 256;
            int i = idx >> 5, k = idx & 31;
            As[k][i] = A[(size_t)(r0 + i) * lda + k0 + k];
        }
#pragma unroll
        for (int l = 0; l < 16; l++) {
            int idx = tid + l * 256;
            int kk = idx >> 7, f = idx & 127;
            Bs[kk][f] = W[(size_t)(k0 + kk) * FDIM + f];
        }
        __syncthreads();
#pragma unroll
        for (int k = 0; k < 32; k++) {
            float av[8];
#pragma unroll
            for (int u = 0; u < 8; u++) av[u] = As[k][ty * 8 + u];
            float4 bv = *(const float4*)&Bs[k][tx * 4];
#pragma unroll
            for (int u = 0; u < 8; u++) {
                acc[u][0] += av[u] * bv.x;
                acc[u][1] += av[u] * bv.y;
                acc[u][2] += av[u] * bv.z;
                acc[u][3] += av[u] * bv.w;
            }
        }
        __syncthreads();
    }
#pragma unroll
    for (int u = 0; u < 8; u++) {
        int r = r0 + ty * 8 + u;
        float4 v = make_float4(acc[u][0], acc[u][1], acc[u][2], acc[u][3]);
        *(float4*)&O[(size_t)r * FDIM + tx * 4] = v;
    }
}

// ---------------- f1/f2 per row ------------------
__global__ void f1f2_kernel(const float* __restrict__ Hmat,
                            const float* __restrict__ Abase, int aHeadStride,
                            float* __restrict__ f1, float* __restrict__ f2,
                            int rowsPerHead)
{
    int warp = (blockIdx.x * blockDim.x + threadIdx.x) >> 5;
    int lane = threadIdx.x & 31;
    int h = warp / rowsPerHead;
    const float* a = Abase + (size_t)h * aHeadStride;
    const float* hr = Hmat + (size_t)warp * FDIM;
    float s1 = 0.f, s2 = 0.f;
#pragma unroll
    for (int u = 0; u < 4; u++) {
        int c = lane + 32 * u;
        float v = hr[c];
        s1 += v * a[c];
        s2 += v * a[FDIM + c];
    }
#pragma unroll
    for (int off = 16; off; off >>= 1) {
        s1 += __shfl_xor_sync(0xffffffffu, s1, off);
        s2 += __shfl_xor_sync(0xffffffffu, s2, off);
    }
    if (lane == 0) { f1[warp] = s1; f2[warp] = s2; }
}

// ---------------- sort f2 per (h,b) + weight arrays + scalar scans ----------
__global__ void sort_kernel(const float* __restrict__ f2,
                            float* __restrict__ f2s, int* __restrict__ perm,
                            float* __restrict__ vv, float* __restrict__ zz,
                            float* __restrict__ sufv, float* __restrict__ prez,
                            float* __restrict__ mf2out)
{
    __shared__ float val[1024];
    __shared__ int   idx[1024];
    __shared__ float sA[1024];
    __shared__ float sB[1024];
    const int hb = blockIdx.x;
    const int tid = threadIdx.x;

    for (int t = tid; t < 1024; t += 512) { val[t] = f2[hb * 1024 + t]; idx[t] = t; }
    __syncthreads();

    for (int k = 2; k <= 1024; k <<= 1) {
        for (int j = k >> 1; j > 0; j >>= 1) {
            for (int t = tid; t < 1024; t += 512) {
                int t2 = t ^ j;
                if (t2 > t) {
                    bool up = ((t & k) == 0);
                    float a = val[t], b = val[t2];
                    if ((a > b) == up) {
                        val[t] = b; val[t2] = a;
                        int ti = idx[t]; idx[t] = idx[t2]; idx[t2] = ti;
                    }
                }
            }
            __syncthreads();
        }
    }

    const float M = val[1023];
    for (int t = tid; t < 1024; t += 512) {
        float fv = val[t];
        f2s[hb * 1024 + t]  = fv;
        perm[hb * 1024 + t] = idx[t];
        float v = __expf(fv - M);
        float z = __expf(0.2f * (fv - M));
        vv[hb * 1024 + t] = v;
        zz[hb * 1024 + t] = z;
        sA[t] = z;
    }
    __syncthreads();

    // inclusive prefix scan of z
    {
        float* src = sA; float* dst = sB;
        for (int off = 1; off < 1024; off <<= 1) {
            for (int t = tid; t < 1024; t += 512)
                dst[t] = src[t] + (t >= off ? src[t - off] : 0.f);
            __syncthreads();
            float* tmp = src; src = dst; dst = tmp;
        }
        for (int t = tid; t < 1024; t += 512)
            prez[hb * 1025 + t + 1] = src[t];
        if (tid == 0) { prez[hb * 1025] = 0.f; mf2out[hb] = M; }
    }
    __syncthreads();

    // inclusive suffix scan of v
    for (int t = tid; t < 1024; t += 512) sA[t] = vv[hb * 1024 + 1023 - t];
    __syncthreads();
    {
        float* src = sA; float* dst = sB;
        for (int off = 1; off < 1024; off <<= 1) {
            for (int t = tid; t < 1024; t += 512)
                dst[t] = src[t] + (t >= off ? src[t - off] : 0.f);
            __syncthreads();
            float* tmp = src; src = dst; dst = tmp;
        }
        for (int t = tid; t < 1024; t += 512)
            sufv[hb * 1025 + 1023 - t] = src[t];
        if (tid == 0) sufv[hb * 1025 + 1024] = 0.f;
    }
}

// ---------------- fused output: chunked prefix + bucketed boundary ----------
// One CTA per (h,b), 1024 threads. 32 chunks of 32 sorted rows.
// smem layout (dynamic):
//   f2s_s[1024] | v_s[1024] | z_s[1024] | PreC[33*128] | SufC[33*128] |
//   Vb[32*128] | perm_s[1024]u16 | tarr[1024]u16 | order[1024]u16 |
//   bcnt[32] | boff[33] | bpos[32]
#define OUT_SMEM_FLOATS (1024*3 + 33*128*2 + 32*128)
#define OUT_SMEM_BYTES  (OUT_SMEM_FLOATS*4 + 3*1024*2 + (32+33+32)*4)

__global__ void out_kernel(const float* __restrict__ V,
                           const float* __restrict__ f1,
                           const float* __restrict__ f2s,
                           const int* __restrict__ perm,
                           const float* __restrict__ vv,
                           const float* __restrict__ zz,
                           const float* __restrict__ sufv,
                           const float* __restrict__ prez,
                           const float* __restrict__ mf2,
                           float* __restrict__ out,
                           int Bdim, int outRowStride, int headColMul, int nElu)
{
    extern __shared__ __align__(16) char smem_raw[];
    float* f2s_s = (float*)smem_raw;             // 1024
    float* v_s   = f2s_s + 1024;                 // 1024
    float* z_s   = v_s + 1024;                   // 1024
    float* PreC  = z_s + 1024;                   // 33*128
    float* SufC  = PreC + 33 * 128;              // 33*128
    float* Vb    = SufC + 33 * 128;              // 32*128
    unsigned short* perm_s = (unsigned short*)(Vb + 32 * 128);
    unsigned short* tarr   = perm_s + 1024;
    unsigned short* order  = tarr + 1024;
    int* bcnt = (int*)(order + 1024);
    int* boff = bcnt + 32;
    int* bpos = boff + 33;

    const int hb = blockIdx.x;
    const int h = hb / Bdim, b = hb % Bdim;
    const int tid = threadIdx.x;   // 1024

    f2s_s[tid]  = f2s[hb * 1024 + tid];
    v_s[tid]    = vv[hb * 1024 + tid];
    z_s[tid]    = zz[hb * 1024 + tid];
    perm_s[tid] = (unsigned short)perm[hb * 1024 + tid];
    if (tid < 32) bcnt[tid] = 0;
    __syncthreads();

    const float* Vh = V + (size_t)hb * NDIM * FDIM;

    // --- pass 1: raw chunk sums. thread (rg=tid>>7, f=tid&127) owns chunks rg+8k.
    {
        const int f = tid & 127;
        const int rg = tid >> 7;
#pragma unroll
        for (int k = 0; k < 4; k++) {
            int c = rg + 8 * k;
            float sv = 0.f, sz = 0.f;
#pragma unroll 4
            for (int r = 0; r < 32; r++) {
                int gr = c * 32 + r;
                float x = Vh[(size_t)perm_s[gr] * FDIM + f];
                sv += v_s[gr] * x;
                sz += z_s[gr] * x;
            }
            SufC[c * 128 + f] = sv;
            PreC[c * 128 + f] = sz;
        }
    }
    __syncthreads();

    // --- chunk suffix/prefix in place (thread per f)
    if (tid < 128) {
        const int f = tid;
        float run = 0.f;
        SufC[32 * 128 + f] = 0.f;
        for (int c = 31; c >= 0; c--) { run += SufC[c * 128 + f]; SufC[c * 128 + f] = run; }
        run = 0.f;
        for (int c = 0; c < 32; c++) { float t = PreC[c * 128 + f]; PreC[c * 128 + f] = run; run += t; }
        PreC[32 * 128 + f] = run;
    }

    // --- queries: binary search threshold, bucket by boundary chunk
    {
        float target = -f1[(size_t)hb * NDIM + tid];
        int lo = 0, hi = 1024;
        while (lo < hi) {
            int mid = (lo + hi) >> 1;
            if (f2s_s[mid] <= target) lo = mid + 1; else hi = mid;
        }
        tarr[tid] = (unsigned short)lo;
        int c = lo >> 5; if (c > 31) c = 31;
        atomicAdd(&bcnt[c], 1);
    }
    __syncthreads();
    if (tid == 0) {
        int s = 0;
        for (int c = 0; c < 32; c++) { boff[c] = s; bpos[c] = s; s += bcnt[c]; }
        boff[32] = s;
    }
    __syncthreads();
    {
        int t = tarr[tid];
        int c = t >> 5; if (c > 31) c = 31;
        int pos = atomicAdd(&bpos[c], 1);
        order[pos] = (unsigned short)tid;
    }
    __syncthreads();

    // --- boundary pass: per chunk, stage V rows, warps finish queries
    const int lane = tid & 31, wid = tid >> 5;
    const float M = mf2[hb];
    for (int c = 0; c < 32; c++) {
#pragma unroll
        for (int j = 0; j < 4; j++) {
            int idx = tid + j * 1024;
            int r = idx >> 7, f = idx & 127;
            Vb[r * 128 + f] = Vh[(size_t)perm_s[c * 32 + r] * FDIM + f];
        }
        __syncthreads();

        for (int p = boff[c] + wid; p < boff[c + 1]; p += 32) {
            int qi = order[p];
            int t  = tarr[qi];
            float f1v = f1[(size_t)hb * NDIM + qi];
            float su = f1v + M;
            float m = lrelu(su);
            float u  = __expf(su - m);
            float w_ = __expf(0.2f * su - m);
            float d  = u * sufv[hb * 1025 + t] + w_ * prez[hb * 1025 + t];
            float inv = 1.f / d;

            const int f0 = lane * 4;
            float4 acc;
            acc.x = u * SufC[(c + 1) * 128 + f0 + 0] + w_ * PreC[c * 128 + f0 + 0];
            acc.y = u * SufC[(c + 1) * 128 + f0 + 1] + w_ * PreC[c * 128 + f0 + 1];
            acc.z = u * SufC[(c + 1) * 128 + f0 + 2] + w_ * PreC[c * 128 + f0 + 2];
            acc.w = u * SufC[(c + 1) * 128 + f0 + 3] + w_ * PreC[c * 128 + f0 + 3];
#pragma unroll 8
            for (int r = 0; r < 32; r++) {
                int gr = c * 32 + r;
                float coef = (gr >= t) ? u * v_s[gr] : w_ * z_s[gr];
                float4 xv = *(const float4*)&Vb[r * 128 + f0];
                acc.x += coef * xv.x;
                acc.y += coef * xv.y;
                acc.z += coef * xv.z;
                acc.w += coef * xv.w;
            }
            float4 o;
            o.x = elu1(acc.x * inv);
            o.y = elu1(acc.y * inv);
            o.z = elu1(acc.z * inv);
            o.w = elu1(acc.w * inv);
            if (nElu == 2) { o.x = elu1(o.x); o.y = elu1(o.y); o.z = elu1(o.z); o.w = elu1(o.w); }
            size_t oidx = ((size_t)(b * NDIM + qi)) * outRowStride + h * headColMul + f0;
            *(float4*)&out[oidx] = o;
        }
        __syncthreads();
    }
}

// -----------------------------------------------------------------------------
extern "C" void kernel_launch(void* const* d_in, const int* in_sizes, int n_in,
                              void* d_out, int out_size)
{
    const float* x       = (const float*)d_in[0];
    // d_in[1] = adj : discarded by the reference math
    const float* W_heads = (const float*)d_in[2];
    const float* a_heads = (const float*)d_in[3];
    const float* W_out   = (const float*)d_in[4];
    const float* a_out   = (const float*)d_in[5];
    float* out = (float*)d_out;

    float *h1, *xc, *h2, *f1a, *f2a, *f1b, *f2b;
    float *f2s, *vv, *zz, *sufv, *prez, *mf2;
    int *perm;
    cudaGetSymbolAddress((void**)&h1,   g_h1);
    cudaGetSymbolAddress((void**)&xc,   g_xc);
    cudaGetSymbolAddress((void**)&h2,   g_h2);
    cudaGetSymbolAddress((void**)&f1a,  g_f1a);
    cudaGetSymbolAddress((void**)&f2a,  g_f2a);
    cudaGetSymbolAddress((void**)&f1b,  g_f1b);
    cudaGetSymbolAddress((void**)&f2b,  g_f2b);
    cudaGetSymbolAddress((void**)&f2s,  g_f2s);
    cudaGetSymbolAddress((void**)&perm, g_perm);
    cudaGetSymbolAddress((void**)&vv,   g_vv);
    cudaGetSymbolAddress((void**)&zz,   g_zz);
    cudaGetSymbolAddress((void**)&sufv, g_sufv);
    cudaGetSymbolAddress((void**)&prez, g_prez);
    cudaGetSymbolAddress((void**)&mf2,  g_mf2);

    static int smem_set = 0;
    if (!smem_set) {
        cudaFuncSetAttribute(out_kernel, cudaFuncAttributeMaxDynamicSharedMemorySize,
                             OUT_SMEM_BYTES);
        smem_set = 1;
    }

    // ---- layer 1 ----
    gemm_kernel<<<dim3(MDIM / 64, HDIM), 256>>>(x, DDIM, W_heads, DDIM * FDIM, DDIM,
                                                h1, MDIM * FDIM);
    f1f2_kernel<<<(HDIM * MDIM) / 8, 256>>>(h1, a_heads, 2 * FDIM, f1a, f2a, MDIM);
    sort_kernel<<<HDIM * BDIM, 512>>>(f2a, f2s, perm, vv, zz, sufv, prez, mf2);
    out_kernel<<<HDIM * BDIM, 1024, OUT_SMEM_BYTES>>>(h1, f1a, f2s, perm, vv, zz,
                                                      sufv, prez, mf2, xc,
                                                      BDIM, HDIM * FDIM, FDIM, 1);

    // ---- layer 2 ----
    gemm_kernel<<<dim3(MDIM / 64, 1), 256>>>(xc, HDIM * FDIM, W_out, 0, HDIM * FDIM,
                                             h2, 0);
    f1f2_kernel<<<MDIM / 8, 256>>>(h2, a_out, 0, f1b, f2b, MDIM);
    sort_kernel<<<BDIM, 512>>>(f2b, f2s, perm, vv, zz, sufv, prez, mf2);
    out_kernel<<<BDIM, 1024, OUT_SMEM_BYTES>>>(h2, f1b, f2s, perm, vv, zz,
                                               sufv, prez, mf2, out,
                                               BDIM, FDIM, 0, 2);
}

// round 4
// speedup vs baseline: 1.1746x; 1.0332x over previous
#include <cuda_runtime.h>
#include <math.h>

#define BDIM 8
#define NDIM 1024
#define DDIM 256
#define HDIM 8
#define FDIM 128
#define MDIM (BDIM * NDIM)   // 8192
#define ALPHA 0.2f

// ---------------- scratch (device globals) ----------------
__device__ float g_h1[HDIM * MDIM * FDIM];      // 33.5 MB
__device__ float g_xc[MDIM * HDIM * FDIM];      // 33.5 MB
__device__ float g_h2[MDIM * FDIM];             // 4 MB
__device__ float g_f1a[HDIM * MDIM];
__device__ float g_f2a[HDIM * MDIM];
__device__ float g_f1b[MDIM];
__device__ float g_f2b[MDIM];
__device__ int   g_perm[64 * 1024];
__device__ float g_vv[64 * 1024];
__device__ float g_zz[64 * 1024];
__device__ int   g_order[64 * 1024];
__device__ int   g_boff[64 * 33];
__device__ float g_qu[64 * 1024];
__device__ float g_qw[64 * 1024];
__device__ float g_csuf[64 * 32 * 128];
__device__ float g_cpre[64 * 32 * 128];

__device__ __forceinline__ float lrelu(float x) { return x > 0.f ? x : ALPHA * x; }
__device__ __forceinline__ float elu1(float x)  { return x > 0.f ? x : expm1f(x); }

// ---------------- SGEMM, BMxBN=BMx128, BK=16, 8x8 micro-tile -----------------
template<int BM, int NTHR>
__global__ void gemm_t(const float* __restrict__ A, int lda,
                       const float* __restrict__ Wbase, int wHeadStride, int K,
                       float* __restrict__ Obase, int oHeadStride)
{
    const int h = blockIdx.y;
    const float* W = Wbase + (size_t)h * wHeadStride;
    float*       O = Obase + (size_t)h * oHeadStride;
    const int r0 = blockIdx.x * BM;

    __shared__ float As[16][BM + 4];
    __shared__ __align__(16) float Bs[16][128];

    const int tid = threadIdx.x;
    const int tx = tid & 15;    // 16 col groups of 8
    const int ty = tid >> 4;    // BM/8 row groups of 8

    float acc[8][8] = {};

    for (int k0 = 0; k0 < K; k0 += 16) {
#pragma unroll
        for (int it = 0; it < (BM * 16) / (4 * NTHR); it++) {
            int idx = tid + it * NTHR;
            int m = idx >> 2, kq = (idx & 3) * 4;
            float4 a = *(const float4*)&A[(size_t)(r0 + m) * lda + k0 + kq];
            As[kq + 0][m] = a.x; As[kq + 1][m] = a.y;
            As[kq + 2][m] = a.z; As[kq + 3][m] = a.w;
        }
#pragma unroll
        for (int it = 0; it < 2048 / (4 * NTHR); it++) {
            int idx = tid + it * NTHR;
            int kk = idx >> 5, f = (idx & 31) * 4;
            *(float4*)&Bs[kk][f] = *(const float4*)&W[(size_t)(k0 + kk) * FDIM + f];
        }
        __syncthreads();
#pragma unroll
        for (int k = 0; k < 16; k++) {
            float4 a0 = *(const float4*)&As[k][ty * 8];
            float4 a1 = *(const float4*)&As[k][ty * 8 + 4];
            float4 b0 = *(const float4*)&Bs[k][tx * 8];
            float4 b1 = *(const float4*)&Bs[k][tx * 8 + 4];
            float av[8] = {a0.x, a0.y, a0.z, a0.w, a1.x, a1.y, a1.z, a1.w};
            float bv[8] = {b0.x, b0.y, b0.z, b0.w, b1.x, b1.y, b1.z, b1.w};
#pragma unroll
            for (int i = 0; i < 8; i++)
#pragma unroll
                for (int j = 0; j < 8; j++) acc[i][j] += av[i] * bv[j];
        }
        __syncthreads();
    }
#pragma unroll
    for (int i = 0; i < 8; i++) {
        int r = r0 + ty * 8 + i;
        *(float4*)&O[(size_t)r * FDIM + tx * 8] =
            make_float4(acc[i][0], acc[i][1], acc[i][2], acc[i][3]);
        *(float4*)&O[(size_t)r * FDIM + tx * 8 + 4] =
            make_float4(acc[i][4], acc[i][5], acc[i][6], acc[i][7]);
    }
}

// ---------------- f1/f2 per row ------------------
__global__ void f1f2_kernel(const float* __restrict__ Hmat,
                            const float* __restrict__ Abase, int aHeadStride,
                            float* __restrict__ f1, float* __restrict__ f2,
                            int rowsPerHead)
{
    int warp = (blockIdx.x * blockDim.x + threadIdx.x) >> 5;
    int lane = threadIdx.x & 31;
    int h = warp / rowsPerHead;
    const float* a = Abase + (size_t)h * aHeadStride;
    const float* hr = Hmat + (size_t)warp * FDIM;
    float s1 = 0.f, s2 = 0.f;
#pragma unroll
    for (int u = 0; u < 4; u++) {
        int c = lane + 32 * u;
        float v = hr[c];
        s1 += v * a[c];
        s2 += v * a[FDIM + c];
    }
#pragma unroll
    for (int off = 16; off; off >>= 1) {
        s1 += __shfl_xor_sync(0xffffffffu, s1, off);
        s2 += __shfl_xor_sync(0xffffffffu, s2, off);
    }
    if (lane == 0) { f1[warp] = s1; f2[warp] = s2; }
}

// ---------------- prep: sort f2, scalar scans, per-query params, buckets ----
__global__ void prep_kernel(const float* __restrict__ f1,
                            const float* __restrict__ f2,
                            int* __restrict__ perm,
                            float* __restrict__ vv, float* __restrict__ zz,
                            int* __restrict__ order, int* __restrict__ boff,
                            float* __restrict__ qu, float* __restrict__ qw)
{
    __shared__ float val[1024];
    __shared__ int   idx[1024];
    __shared__ float sA[1024], sB[1024];
    __shared__ float prez_s[1025], sufv_s[1025];
    __shared__ int bcnt[32], boffs[33], bpos[32];

    const int hb = blockIdx.x, tid = threadIdx.x;   // 1024 threads

    val[tid] = f2[hb * 1024 + tid];
    idx[tid] = tid;
    if (tid < 32) bcnt[tid] = 0;
    __syncthreads();

    // bitonic sort ascending (value+index)
    for (int k = 2; k <= 1024; k <<= 1) {
        for (int j = k >> 1; j; j >>= 1) {
            int t2 = tid ^ j;
            if (t2 > tid) {
                bool up = ((tid & k) == 0);
                float a = val[tid], b2 = val[t2];
                if ((a > b2) == up) {
                    val[tid] = b2; val[t2] = a;
                    int ti = idx[tid]; idx[tid] = idx[t2]; idx[t2] = ti;
                }
            }
            __syncthreads();
        }
    }

    const float M = val[1023];
    {
        float fv = val[tid];
        float v = __expf(fv - M);
        float z = __expf(0.2f * (fv - M));
        vv[hb * 1024 + tid] = v;
        zz[hb * 1024 + tid] = z;
        perm[hb * 1024 + tid] = idx[tid];
        sA[tid] = z;
    }
    __syncthreads();

    // inclusive prefix scan of z
    {
        float* src = sA; float* dst = sB;
        for (int off = 1; off < 1024; off <<= 1) {
            dst[tid] = src[tid] + (tid >= off ? src[tid - off] : 0.f);
            __syncthreads();
            float* tmp = src; src = dst; dst = tmp;
        }
        prez_s[tid + 1] = src[tid];
        if (tid == 0) prez_s[0] = 0.f;
    }
    __syncthreads();

    // inclusive suffix scan of v (scan reversed)
    sA[tid] = __expf(val[1023 - tid] - M);
    __syncthreads();
    {
        float* src = sA; float* dst = sB;
        for (int off = 1; off < 1024; off <<= 1) {
            dst[tid] = src[tid] + (tid >= off ? src[tid - off] : 0.f);
            __syncthreads();
            float* tmp = src; src = dst; dst = tmp;
        }
        sufv_s[tid] = src[1023 - tid];
        if (tid == 0) sufv_s[1024] = 0.f;
    }
    __syncthreads();

    // per-query: threshold search + softmax params
    float f1v = f1[hb * 1024 + tid];
    float target = -f1v;
    int lo = 0, hi = 1024;
    while (lo < hi) {
        int mid = (lo + hi) >> 1;
        if (val[mid] <= target) lo = mid + 1; else hi = mid;
    }
    const int t = lo;
    float su = f1v + M;
    float m = lrelu(su);
    float u = __expf(su - m);
    float w = __expf(0.2f * su - m);
    float d = u * sufv_s[t] + w * prez_s[t];
    float invd = 1.f / d;
    qu[hb * 1024 + tid] = u * invd;
    qw[hb * 1024 + tid] = w * invd;

    int c = t >> 5; if (c > 31) c = 31;
    atomicAdd(&bcnt[c], 1);
    __syncthreads();
    if (tid == 0) {
        int s = 0;
        for (int q = 0; q < 32; q++) { boffs[q] = s; bpos[q] = s; s += bcnt[q]; }
        boffs[32] = s;
    }
    __syncthreads();
    int pos = atomicAdd(&bpos[c], 1);
    order[hb * 1024 + pos] = tid | (t << 12);
    if (tid < 33) boff[hb * 33 + tid] = boffs[tid];
}

// ---------------- chunk raw weighted sums ------------------------------------
__global__ void chunk_kernel(const float* __restrict__ V,
                             const int* __restrict__ perm,
                             const float* __restrict__ vv,
                             const float* __restrict__ zz,
                             float* __restrict__ csuf, float* __restrict__ cpre)
{
    __shared__ int ps[32];
    __shared__ float vs[32], zs[32];
    const int c = blockIdx.x & 31, hb = blockIdx.x >> 5;
    const int f = threadIdx.x;   // 128

    if (f < 32) {
        int g = hb * 1024 + c * 32 + f;
        ps[f] = perm[g]; vs[f] = vv[g]; zs[f] = zz[g];
    }
    __syncthreads();

    const float* Vh = V + (size_t)hb * NDIM * FDIM;
    float sv = 0.f, sz = 0.f;
#pragma unroll 8
    for (int r = 0; r < 32; r++) {
        float x = Vh[(size_t)ps[r] * FDIM + f];
        sv += vs[r] * x;
        sz += zs[r] * x;
    }
    csuf[(size_t)(hb * 32 + c) * 128 + f] = sv;
    cpre[(size_t)(hb * 32 + c) * 128 + f] = sz;
}

// ---------------- output: per-chunk boundary finish + elu --------------------
__global__ void outd_kernel(const float* __restrict__ V,
                            const int* __restrict__ perm,
                            const float* __restrict__ vv,
                            const float* __restrict__ zz,
                            const float* __restrict__ csuf,
                            const float* __restrict__ cpre,
                            const int* __restrict__ order,
                            const int* __restrict__ boff,
                            const float* __restrict__ qu,
                            const float* __restrict__ qw,
                            float* __restrict__ out,
                            int Bdim, int outRowStride, int headColMul, int nElu)
{
    __shared__ __align__(16) float Vb[32 * 128];
    __shared__ float bsuf[128], bpre[128];
    __shared__ float vs[32], zs[32];
    __shared__ int ps[32];

    const int c = blockIdx.x & 31, hb = blockIdx.x >> 5;
    const int h = hb / Bdim, b = hb % Bdim;
    const int tid = threadIdx.x;   // 256

    if (tid < 32) {
        int g = hb * 1024 + c * 32 + tid;
        ps[tid] = perm[g]; vs[tid] = vv[g]; zs[tid] = zz[g];
    }
    __syncthreads();

    const float* Vh = V + (size_t)hb * NDIM * FDIM;
#pragma unroll
    for (int j = 0; j < 16; j++) {
        int e = tid + j * 256;
        int r = e >> 7, f = e & 127;
        Vb[r * 128 + f] = Vh[(size_t)ps[r] * FDIM + f];
    }
    if (tid < 128) {
        float s = 0.f;
        for (int cc = c + 1; cc < 32; cc++) s += csuf[(size_t)(hb * 32 + cc) * 128 + tid];
        bsuf[tid] = s;
    } else {
        int f = tid - 128;
        float s = 0.f;
        for (int cc = 0; cc < c; cc++) s += cpre[(size_t)(hb * 32 + cc) * 128 + f];
        bpre[f] = s;
    }
    __syncthreads();

    const int start = boff[hb * 33 + c], end = boff[hb * 33 + c + 1];
    const int lane = tid & 31, wid = tid >> 5;
    for (int p = start + wid; p < end; p += 8) {
        int e = order[hb * 1024 + p];
        int qi = e & 0xFFF;
        int t  = e >> 12;
        float u = qu[hb * 1024 + qi];
        float w = qw[hb * 1024 + qi];
        const int f0 = lane * 4;
        float4 acc;
        acc.x = u * bsuf[f0 + 0] + w * bpre[f0 + 0];
        acc.y = u * bsuf[f0 + 1] + w * bpre[f0 + 1];
        acc.z = u * bsuf[f0 + 2] + w * bpre[f0 + 2];
        acc.w = u * bsuf[f0 + 3] + w * bpre[f0 + 3];
#pragma unroll 8
        for (int r = 0; r < 32; r++) {
            int gr = c * 32 + r;
            float coef = (gr >= t) ? u * vs[r] : w * zs[r];
            float4 xv = *(const float4*)&Vb[r * 128 + f0];
            acc.x += coef * xv.x;
            acc.y += coef * xv.y;
            acc.z += coef * xv.z;
            acc.w += coef * xv.w;
        }
        float4 o;
        o.x = elu1(acc.x); o.y = elu1(acc.y); o.z = elu1(acc.z); o.w = elu1(acc.w);
        if (nElu == 2) { o.x = elu1(o.x); o.y = elu1(o.y); o.z = elu1(o.z); o.w = elu1(o.w); }
        size_t oidx = ((size_t)(b * NDIM + qi)) * outRowStride + h * headColMul + f0;
        *(float4*)&out[oidx] = o;
    }
}

// -----------------------------------------------------------------------------
extern "C" void kernel_launch(void* const* d_in, const int* in_sizes, int n_in,
                              void* d_out, int out_size)
{
    const float* x       = (const float*)d_in[0];
    // d_in[1] = adj : discarded by the reference math
    const float* W_heads = (const float*)d_in[2];
    const float* a_heads = (const float*)d_in[3];
    const float* W_out   = (const float*)d_in[4];
    const float* a_out   = (const float*)d_in[5];
    float* out = (float*)d_out;

    float *h1, *xc, *h2, *f1a, *f2a, *f1b, *f2b;
    float *vv, *zz, *qu, *qw, *csuf, *cpre;
    int *perm, *order, *boff;
    cudaGetSymbolAddress((void**)&h1,    g_h1);
    cudaGetSymbolAddress((void**)&xc,    g_xc);
    cudaGetSymbolAddress((void**)&h2,    g_h2);
    cudaGetSymbolAddress((void**)&f1a,   g_f1a);
    cudaGetSymbolAddress((void**)&f2a,   g_f2a);
    cudaGetSymbolAddress((void**)&f1b,   g_f1b);
    cudaGetSymbolAddress((void**)&f2b,   g_f2b);
    cudaGetSymbolAddress((void**)&perm,  g_perm);
    cudaGetSymbolAddress((void**)&vv,    g_vv);
    cudaGetSymbolAddress((void**)&zz,    g_zz);
    cudaGetSymbolAddress((void**)&order, g_order);
    cudaGetSymbolAddress((void**)&boff,  g_boff);
    cudaGetSymbolAddress((void**)&qu,    g_qu);
    cudaGetSymbolAddress((void**)&qw,    g_qw);
    cudaGetSymbolAddress((void**)&csuf,  g_csuf);
    cudaGetSymbolAddress((void**)&cpre,  g_cpre);

    // ---- layer 1 ----
    gemm_t<128, 256><<<dim3(MDIM / 128, HDIM), 256>>>(x, DDIM, W_heads, DDIM * FDIM,
                                                      DDIM, h1, MDIM * FDIM);
    f1f2_kernel<<<(HDIM * MDIM) / 8, 256>>>(h1, a_heads, 2 * FDIM, f1a, f2a, MDIM);
    prep_kernel<<<HDIM * BDIM, 1024>>>(f1a, f2a, perm, vv, zz, order, boff, qu, qw);
    chunk_kernel<<<HDIM * BDIM * 32, 128>>>(h1, perm, vv, zz, csuf, cpre);
    outd_kernel<<<HDIM * BDIM * 32, 256>>>(h1, perm, vv, zz, csuf, cpre, order, boff,
                                           qu, qw, xc, BDIM, HDIM * FDIM, FDIM, 1);

    // ---- layer 2 ----
    gemm_t<64, 128><<<dim3(MDIM / 64, 1), 128>>>(xc, HDIM * FDIM, W_out, 0,
                                                 HDIM * FDIM, h2, 0);
    f1f2_kernel<<<MDIM / 8, 256>>>(h2, a_out, 0, f1b, f2b, MDIM);
    prep_kernel<<<BDIM, 1024>>>(f1b, f2b, perm, vv, zz, order, boff, qu, qw);
    chunk_kernel<<<BDIM * 32, 128>>>(h2, perm, vv, zz, csuf, cpre);
    outd_kernel<<<BDIM * 32, 256>>>(h2, perm, vv, zz, csuf, cpre, order, boff,
                                    qu, qw, out, BDIM, FDIM, 0, 2);
}

// round 6
// speedup vs baseline: 1.3779x; 1.1731x over previous
#include <cuda_runtime.h>
#include <cuda_bf16.h>
#include <math.h>
#include <cstdint>

#define BDIM 8
#define NDIM 1024
#define DDIM 256
#define HDIM 8
#define FDIM 128
#define MDIM (BDIM * NDIM)   // 8192
#define ALPHA 0.2f

// ---------------- scratch (device globals) ----------------
__device__ float g_h1[HDIM * MDIM * FDIM];            // 33.5 MB (V for layer1)
__device__ float g_h2[MDIM * FDIM];                   // 4 MB (V for layer2)
__device__ __nv_bfloat16 g_xh[MDIM * DDIM];
__device__ __nv_bfloat16 g_xl[MDIM * DDIM];
__device__ __nv_bfloat16 g_w1h[HDIM * FDIM * DDIM];   // W1^T [h][n][k]
__device__ __nv_bfloat16 g_w1l[HDIM * FDIM * DDIM];
__device__ __nv_bfloat16 g_w2h[FDIM * (HDIM * FDIM)]; // W2^T [n][k]
__device__ __nv_bfloat16 g_w2l[FDIM * (HDIM * FDIM)];
__device__ __nv_bfloat16 g_xch[MDIM * HDIM * FDIM];   // xc hi (layer2 A)
__device__ __nv_bfloat16 g_xcl[MDIM * HDIM * FDIM];
__device__ float g_f1a[HDIM * MDIM];
__device__ float g_f2a[HDIM * MDIM];
__device__ float g_f1b[MDIM];
__device__ float g_f2b[MDIM];
__device__ int   g_perm[64 * 1024];
__device__ float g_vv[64 * 1024];
__device__ float g_zz[64 * 1024];
__device__ int   g_order[64 * 1024];
__device__ int   g_boff[64 * 33];
__device__ float g_qu[64 * 1024];
__device__ float g_qw[64 * 1024];
__device__ float g_csuf[64 * 32 * 128];
__device__ float g_cpre[64 * 32 * 128];

__device__ __forceinline__ float lrelu(float x) { return x > 0.f ? x : ALPHA * x; }
__device__ __forceinline__ float elu1(float x)  { return x > 0.f ? x : expm1f(x); }

__device__ __forceinline__ uint32_t smem_to_u32(const void* p) {
    uint32_t a;
    asm("{ .reg .u64 t; cvta.to.shared.u64 t, %1; cvt.u32.u64 %0, t; }"
        : "=r"(a) : "l"(p));
    return a;
}

#define LDSM4(r0, r1, r2, r3, addr) \
    asm volatile("ldmatrix.sync.aligned.m8n8.x4.shared.b16 {%0,%1,%2,%3}, [%4];" \
                 : "=r"(r0), "=r"(r1), "=r"(r2), "=r"(r3) : "r"(addr))

#define MMA16816(c, a, b) \
    asm volatile("mma.sync.aligned.m16n8k16.row.col.f32.bf16.bf16.f32 " \
                 "{%0,%1,%2,%3}, {%4,%5,%6,%7}, {%8,%9}, {%0,%1,%2,%3};" \
                 : "+f"((c)[0]), "+f"((c)[1]), "+f"((c)[2]), "+f"((c)[3]) \
                 : "r"((a)[0]), "r"((a)[1]), "r"((a)[2]), "r"((a)[3]), \
                   "r"((b)[0]), "r"((b)[1]))

// ================= conversions =================
__global__ void splitf_kernel(const float* __restrict__ src,
                              __nv_bfloat16* __restrict__ hi,
                              __nv_bfloat16* __restrict__ lo, int n)
{
    int i = blockIdx.x * 256 + threadIdx.x;
    if (i < n) {
        float v = src[i];
        __nv_bfloat16 h = __float2bfloat16(v);
        hi[i] = h;
        lo[i] = __float2bfloat16(v - __bfloat162float(h));
    }
}

// W[h][k][128] -> Wt[h][n][K] hi/lo
__global__ void trw_kernel(const float* __restrict__ W,
                           __nv_bfloat16* __restrict__ oh,
                           __nv_bfloat16* __restrict__ ol, int K)
{
    int idx = blockIdx.x * 256 + threadIdx.x;
    int h = idx / (K * 128);
    int rem = idx % (K * 128);
    int k = rem >> 7, n = rem & 127;
    float v = W[idx];
    __nv_bfloat16 hh = __float2bfloat16(v);
    int o = h * K * 128 + n * K + k;
    oh[o] = hh;
    ol[o] = __float2bfloat16(v - __bfloat162float(hh));
}

// ================= bf16x3 HMMA GEMM =================
// O[BM x 128] = (Ah+Al) @ (Bh+Bl)^T per CTA; B stored transposed [n][K].
// 256 threads = 8 warps; warp tile (BM/WARPS_M) x (128/WARPS_N); BK=32.
template<int BM, int WARPS_M, int WARPS_N>
__global__ void __launch_bounds__(256, 1)
mma_gemm(const __nv_bfloat16* __restrict__ Ah, const __nv_bfloat16* __restrict__ Al,
         int K,
         const __nv_bfloat16* __restrict__ Bh_base,
         const __nv_bfloat16* __restrict__ Bl_base,
         float* __restrict__ O_base, long long oHeadStride)
{
    constexpr int TM = BM / WARPS_M;          // 64
    constexpr int TN = 128 / WARPS_N;         // 32 or 16
    constexpr int MT = TM / 16;               // 4
    constexpr int NT = TN / 8;                // 4 or 2
    constexpr int RSTR = 80;                  // smem row stride bytes (32 bf16 + 16B pad)

    __shared__ __align__(16) char smem[(2 * BM + 2 * 128) * RSTR];
    char* sAh = smem;
    char* sAl = smem + BM * RSTR;
    char* sBh = smem + 2 * BM * RSTR;
    char* sBl = smem + (2 * BM + 128) * RSTR;

    const int h = blockIdx.y;
    const __nv_bfloat16* Bh = Bh_base + (size_t)h * 128 * K;
    const __nv_bfloat16* Bl = Bl_base + (size_t)h * 128 * K;
    float* O = O_base + (size_t)h * oHeadStride;
    const int r0 = blockIdx.x * BM;

    const int tid = threadIdx.x, wid = tid >> 5, lane = tid & 31;
    const int warp_m = wid % WARPS_M, warp_n = wid / WARPS_M;
    const int g = lane >> 2, t = lane & 3;

    const uint32_t sbase = smem_to_u32(smem);
    // ldmatrix lane addresses (A: lanes0-7 rows0-7/k0, 8-15 rows8-15/k0, 16-23 rows0-7/k8, 24-31 rows8-15/k8)
    const uint32_t aAddr = sbase + (uint32_t)(warp_m * TM + (lane & 15)) * RSTR
                           + (uint32_t)((lane >> 4) * 16);
    // B: lanes0-7 n0-7/k0, 8-15 n0-7/k8, 16-23 n8-15/k0, 24-31 n8-15/k8
    const uint32_t bAddr = sbase + (uint32_t)(2 * BM * RSTR)
                           + (uint32_t)((warp_n * TN + (lane & 7) + ((lane & 16) ? 8 : 0)) * RSTR)
                           + (uint32_t)((lane & 8) ? 16 : 0);

    float acc[MT][NT][4] = {};

    for (int k0 = 0; k0 < K; k0 += 32) {
#pragma unroll
        for (int it = 0; it < (BM * 4) / 256; it++) {
            int idx = tid + it * 256;
            int m = idx >> 2, kc = idx & 3;
            int doff = m * RSTR + kc * 16;
            size_t soff = (size_t)(r0 + m) * K + k0 + kc * 8;
            *(uint4*)(sAh + doff) = *(const uint4*)(Ah + soff);
            *(uint4*)(sAl + doff) = *(const uint4*)(Al + soff);
        }
#pragma unroll
        for (int it = 0; it < 2; it++) {
            int idx = tid + it * 256;
            int n = idx >> 2, kc = idx & 3;
            int doff = n * RSTR + kc * 16;
            size_t soff = (size_t)n * K + k0 + kc * 8;
            *(uint4*)(sBh + doff) = *(const uint4*)(Bh + soff);
            *(uint4*)(sBl + doff) = *(const uint4*)(Bl + soff);
        }
        __syncthreads();

#pragma unroll
        for (int s = 0; s < 2; s++) {
            uint32_t bh[NT][2], bl[NT][2];
#pragma unroll
            for (int jj = 0; jj < NT / 2; jj++) {
                uint32_t ad = bAddr + (uint32_t)(jj * 16 * RSTR + s * 32);
                LDSM4(bh[2 * jj][0], bh[2 * jj][1], bh[2 * jj + 1][0], bh[2 * jj + 1][1], ad);
                LDSM4(bl[2 * jj][0], bl[2 * jj][1], bl[2 * jj + 1][0], bl[2 * jj + 1][1],
                      ad + 128 * RSTR);
            }
#pragma unroll
            for (int i = 0; i < MT; i++) {
                uint32_t a_h[4], a_l[4];
                uint32_t ad = aAddr + (uint32_t)(i * 16 * RSTR + s * 32);
                LDSM4(a_h[0], a_h[1], a_h[2], a_h[3], ad);
                LDSM4(a_l[0], a_l[1], a_l[2], a_l[3], ad + BM * RSTR);
#pragma unroll
                for (int j = 0; j < NT; j++) {
                    MMA16816(acc[i][j], a_h, bh[j]);
                    MMA16816(acc[i][j], a_h, bl[j]);
                    MMA16816(acc[i][j], a_l, bh[j]);
                }
            }
        }
        __syncthreads();
    }

#pragma unroll
    for (int i = 0; i < MT; i++)
#pragma unroll
        for (int j = 0; j < NT; j++) {
            int row = r0 + warp_m * TM + i * 16 + g;
            int col = warp_n * TN + j * 8 + 2 * t;
            *(float2*)&O[(size_t)row * FDIM + col] =
                make_float2(acc[i][j][0], acc[i][j][1]);
            *(float2*)&O[(size_t)(row + 8) * FDIM + col] =
                make_float2(acc[i][j][2], acc[i][j][3]);
        }
}

// ---------------- f1/f2 per row ------------------
__global__ void f1f2_kernel(const float* __restrict__ Hmat,
                            const float* __restrict__ Abase, int aHeadStride,
                            float* __restrict__ f1, float* __restrict__ f2,
                            int rowsPerHead)
{
    int warp = (blockIdx.x * blockDim.x + threadIdx.x) >> 5;
    int lane = threadIdx.x & 31;
    int h = warp / rowsPerHead;
    const float* a = Abase + (size_t)h * aHeadStride;
    const float* hr = Hmat + (size_t)warp * FDIM;
    float s1 = 0.f, s2 = 0.f;
#pragma unroll
    for (int u = 0; u < 4; u++) {
        int c = lane + 32 * u;
        float v = hr[c];
        s1 += v * a[c];
        s2 += v * a[FDIM + c];
    }
#pragma unroll
    for (int off = 16; off; off >>= 1) {
        s1 += __shfl_xor_sync(0xffffffffu, s1, off);
        s2 += __shfl_xor_sync(0xffffffffu, s2, off);
    }
    if (lane == 0) { f1[warp] = s1; f2[warp] = s2; }
}

// ---------------- prep: sort f2, scalar scans, per-query params, buckets ----
__global__ void prep_kernel(const float* __restrict__ f1,
                            const float* __restrict__ f2,
                            int* __restrict__ perm,
                            float* __restrict__ vv, float* __restrict__ zz,
                            int* __restrict__ order, int* __restrict__ boff,
                            float* __restrict__ qu, float* __restrict__ qw)
{
    __shared__ float val[1024];
    __shared__ int   idx[1024];
    __shared__ float sA[1024], sB[1024];
    __shared__ float prez_s[1025], sufv_s[1025];
    __shared__ int bcnt[32], boffs[33], bpos[32];

    const int hb = blockIdx.x, tid = threadIdx.x;   // 1024 threads

    val[tid] = f2[hb * 1024 + tid];
    idx[tid] = tid;
    if (tid < 32) bcnt[tid] = 0;
    __syncthreads();

    for (int k = 2; k <= 1024; k <<= 1) {
        for (int j = k >> 1; j; j >>= 1) {
            int t2 = tid ^ j;
            if (t2 > tid) {
                bool up = ((tid & k) == 0);
                float a = val[tid], b2 = val[t2];
                if ((a > b2) == up) {
                    val[tid] = b2; val[t2] = a;
                    int ti = idx[tid]; idx[tid] = idx[t2]; idx[t2] = ti;
                }
            }
            __syncthreads();
        }
    }

    const float M = val[1023];
    {
        float fv = val[tid];
        float v = __expf(fv - M);
        float z = __expf(0.2f * (fv - M));
        vv[hb * 1024 + tid] = v;
        zz[hb * 1024 + tid] = z;
        perm[hb * 1024 + tid] = idx[tid];
        sA[tid] = z;
    }
    __syncthreads();

    {
        float* src = sA; float* dst = sB;
        for (int off = 1; off < 1024; off <<= 1) {
            dst[tid] = src[tid] + (tid >= off ? src[tid - off] : 0.f);
            __syncthreads();
            float* tmp = src; src = dst; dst = tmp;
        }
        prez_s[tid + 1] = src[tid];
        if (tid == 0) prez_s[0] = 0.f;
    }
    __syncthreads();

    sA[tid] = __expf(val[1023 - tid] - M);
    __syncthreads();
    {
        float* src = sA; float* dst = sB;
        for (int off = 1; off < 1024; off <<= 1) {
            dst[tid] = src[tid] + (tid >= off ? src[tid - off] : 0.f);
            __syncthreads();
            float* tmp = src; src = dst; dst = tmp;
        }
        sufv_s[tid] = src[1023 - tid];
        if (tid == 0) sufv_s[1024] = 0.f;
    }
    __syncthreads();

    float f1v = f1[hb * 1024 + tid];
    float target = -f1v;
    int lo = 0, hi = 1024;
    while (lo < hi) {
        int mid = (lo + hi) >> 1;
        if (val[mid] <= target) lo = mid + 1; else hi = mid;
    }
    const int t = lo;
    float su = f1v + M;
    float m = lrelu(su);
    float u = __expf(su - m);
    float w = __expf(0.2f * su - m);
    float d = u * sufv_s[t] + w * prez_s[t];
    float invd = 1.f / d;
    qu[hb * 1024 + tid] = u * invd;
    qw[hb * 1024 + tid] = w * invd;

    int c = t >> 5; if (c > 31) c = 31;
    atomicAdd(&bcnt[c], 1);
    __syncthreads();
    if (tid == 0) {
        int s = 0;
        for (int q = 0; q < 32; q++) { boffs[q] = s; bpos[q] = s; s += bcnt[q]; }
        boffs[32] = s;
    }
    __syncthreads();
    int pos = atomicAdd(&bpos[c], 1);
    order[hb * 1024 + pos] = tid | (t << 12);
    if (tid < 33) boff[hb * 33 + tid] = boffs[tid];
}

// ---------------- chunk raw weighted sums ------------------------------------
__global__ void chunk_kernel(const float* __restrict__ V,
                             const int* __restrict__ perm,
                             const float* __restrict__ vv,
                             const float* __restrict__ zz,
                             float* __restrict__ csuf, float* __restrict__ cpre)
{
    __shared__ int ps[32];
    __shared__ float vs[32], zs[32];
    const int c = blockIdx.x & 31, hb = blockIdx.x >> 5;
    const int f = threadIdx.x;   // 128

    if (f < 32) {
        int g = hb * 1024 + c * 32 + f;
        ps[f] = perm[g]; vs[f] = vv[g]; zs[f] = zz[g];
    }
    __syncthreads();

    const float* Vh = V + (size_t)hb * NDIM * FDIM;
    float sv = 0.f, sz = 0.f;
#pragma unroll 8
    for (int r = 0; r < 32; r++) {
        float x = Vh[(size_t)ps[r] * FDIM + f];
        sv += vs[r] * x;
        sz += zs[r] * x;
    }
    csuf[(size_t)(hb * 32 + c) * 128 + f] = sv;
    cpre[(size_t)(hb * 32 + c) * 128 + f] = sz;
}

// ---------------- output: per-chunk boundary finish + elu --------------------
__global__ void outd_kernel(const float* __restrict__ V,
                            const int* __restrict__ perm,
                            const float* __restrict__ vv,
                            const float* __restrict__ zz,
                            const float* __restrict__ csuf,
                            const float* __restrict__ cpre,
                            const int* __restrict__ order,
                            const int* __restrict__ boff,
                            const float* __restrict__ qu,
                            const float* __restrict__ qw,
                            float* __restrict__ out,
                            __nv_bfloat16* __restrict__ outH,
                            __nv_bfloat16* __restrict__ outL,
                            int Bdim, int outRowStride, int headColMul, int nElu)
{
    __shared__ __align__(16) float Vb[32 * 128];
    __shared__ float bsuf[128], bpre[128];
    __shared__ float vs[32], zs[32];
    __shared__ int ps[32];

    const int c = blockIdx.x & 31, hb = blockIdx.x >> 5;
    const int h = hb / Bdim, b = hb % Bdim;
    const int tid = threadIdx.x;   // 256

    if (tid < 32) {
        int g = hb * 1024 + c * 32 + tid;
        ps[tid] = perm[g]; vs[tid] = vv[g]; zs[tid] = zz[g];
    }
    __syncthreads();

    const float* Vh = V + (size_t)hb * NDIM * FDIM;
#pragma unroll
    for (int j = 0; j < 16; j++) {
        int e = tid + j * 256;
        int r = e >> 7, f = e & 127;
        Vb[r * 128 + f] = Vh[(size_t)ps[r] * FDIM + f];
    }
    if (tid < 128) {
        float s = 0.f;
        for (int cc = c + 1; cc < 32; cc++) s += csuf[(size_t)(hb * 32 + cc) * 128 + tid];
        bsuf[tid] = s;
    } else {
        int f = tid - 128;
        float s = 0.f;
        for (int cc = 0; cc < c; cc++) s += cpre[(size_t)(hb * 32 + cc) * 128 + f];
        bpre[f] = s;
    }
    __syncthreads();

    const int start = boff[hb * 33 + c], end = boff[hb * 33 + c + 1];
    const int lane = tid & 31, wid = tid >> 5;
    for (int p = start + wid; p < end; p += 8) {
        int e = order[hb * 1024 + p];
        int qi = e & 0xFFF;
        int t  = e >> 12;
        float u = qu[hb * 1024 + qi];
        float w = qw[hb * 1024 + qi];
        const int f0 = lane * 4;
        float4 acc;
        acc.x = u * bsuf[f0 + 0] + w * bpre[f0 + 0];
        acc.y = u * bsuf[f0 + 1] + w * bpre[f0 + 1];
        acc.z = u * bsuf[f0 + 2] + w * bpre[f0 + 2];
        acc.w = u * bsuf[f0 + 3] + w * bpre[f0 + 3];
#pragma unroll 8
        for (int r = 0; r < 32; r++) {
            int gr = c * 32 + r;
            float coef = (gr >= t) ? u * vs[r] : w * zs[r];
            float4 xv = *(const float4*)&Vb[r * 128 + f0];
            acc.x += coef * xv.x;
            acc.y += coef * xv.y;
            acc.z += coef * xv.z;
            acc.w += coef * xv.w;
        }
        float4 o;
        o.x = elu1(acc.x); o.y = elu1(acc.y); o.z = elu1(acc.z); o.w = elu1(acc.w);
        if (nElu == 2) { o.x = elu1(o.x); o.y = elu1(o.y); o.z = elu1(o.z); o.w = elu1(o.w); }
        size_t oidx = ((size_t)(b * NDIM + qi)) * outRowStride + h * headColMul + f0;
        if (outH) {
            float vals[4] = {o.x, o.y, o.z, o.w};
#pragma unroll
            for (int q = 0; q < 4; q++) {
                __nv_bfloat16 hi = __float2bfloat16(vals[q]);
                outH[oidx + q] = hi;
                outL[oidx + q] = __float2bfloat16(vals[q] - __bfloat162float(hi));
            }
        } else {
            *(float4*)&out[oidx] = o;
        }
    }
}

// -----------------------------------------------------------------------------
extern "C" void kernel_launch(void* const* d_in, const int* in_sizes, int n_in,
                              void* d_out, int out_size)
{
    const float* x       = (const float*)d_in[0];
    // d_in[1] = adj : discarded by the reference math
    const float* W_heads = (const float*)d_in[2];
    const float* a_heads = (const float*)d_in[3];
    const float* W_out   = (const float*)d_in[4];
    const float* a_out   = (const float*)d_in[5];
    float* out = (float*)d_out;

    float *h1, *h2, *f1a, *f2a, *f1b, *f2b;
    float *vv, *zz, *qu, *qw, *csuf, *cpre;
    int *perm, *order, *boff;
    __nv_bfloat16 *xh, *xl, *w1h, *w1l, *w2h, *w2l, *xch, *xcl;
    cudaGetSymbolAddress((void**)&h1,    g_h1);
    cudaGetSymbolAddress((void**)&h2,    g_h2);
    cudaGetSymbolAddress((void**)&f1a,   g_f1a);
    cudaGetSymbolAddress((void**)&f2a,   g_f2a);
    cudaGetSymbolAddress((void**)&f1b,   g_f1b);
    cudaGetSymbolAddress((void**)&f2b,   g_f2b);
    cudaGetSymbolAddress((void**)&perm,  g_perm);
    cudaGetSymbolAddress((void**)&vv,    g_vv);
    cudaGetSymbolAddress((void**)&zz,    g_zz);
    cudaGetSymbolAddress((void**)&order, g_order);
    cudaGetSymbolAddress((void**)&boff,  g_boff);
    cudaGetSymbolAddress((void**)&qu,    g_qu);
    cudaGetSymbolAddress((void**)&qw,    g_qw);
    cudaGetSymbolAddress((void**)&csuf,  g_csuf);
    cudaGetSymbolAddress((void**)&cpre,  g_cpre);
    cudaGetSymbolAddress((void**)&xh,    g_xh);
    cudaGetSymbolAddress((void**)&xl,    g_xl);
    cudaGetSymbolAddress((void**)&w1h,   g_w1h);
    cudaGetSymbolAddress((void**)&w1l,   g_w1l);
    cudaGetSymbolAddress((void**)&w2h,   g_w2h);
    cudaGetSymbolAddress((void**)&w2l,   g_w2l);
    cudaGetSymbolAddress((void**)&xch,   g_xch);
    cudaGetSymbolAddress((void**)&xcl,   g_xcl);

    // conversions
    splitf_kernel<<<(MDIM * DDIM) / 256, 256>>>(x, xh, xl, MDIM * DDIM);
    trw_kernel<<<(HDIM * DDIM * FDIM) / 256, 256>>>(W_heads, w1h, w1l, DDIM);
    trw_kernel<<<(HDIM * FDIM * FDIM) / 256, 256>>>(W_out, w2h, w2l, HDIM * FDIM);

    // ---- layer 1: h1 = x @ W1 (bf16x3 HMMA) ----
    mma_gemm<128, 2, 4><<<dim3(MDIM / 128, HDIM), 256>>>(
        xh, xl, DDIM, w1h, w1l, h1, (long long)MDIM * FDIM);
    f1f2_kernel<<<(HDIM * MDIM) / 8, 256>>>(h1, a_heads, 2 * FDIM, f1a, f2a, MDIM);
    prep_kernel<<<HDIM * BDIM, 1024>>>(f1a, f2a, perm, vv, zz, order, boff, qu, qw);
    chunk_kernel<<<HDIM * BDIM * 32, 128>>>(h1, perm, vv, zz, csuf, cpre);
    outd_kernel<<<HDIM * BDIM * 32, 256>>>(h1, perm, vv, zz, csuf, cpre, order, boff,
                                           qu, qw, nullptr, xch, xcl,
                                           BDIM, HDIM * FDIM, FDIM, 1);

    // ---- layer 2: h2 = xc @ W2 ----
    mma_gemm<64, 1, 8><<<dim3(MDIM / 64, 1), 256>>>(
        xch, xcl, HDIM * FDIM, w2h, w2l, h2, 0);
    f1f2_kernel<<<MDIM / 8, 256>>>(h2, a_out, 0, f1b, f2b, MDIM);
    prep_kernel<<<BDIM, 1024>>>(f1b, f2b, perm, vv, zz, order, boff, qu, qw);
    chunk_kernel<<<BDIM * 32, 128>>>(h2, perm, vv, zz, csuf, cpre);
    outd_kernel<<<BDIM * 32, 256>>>(h2, perm, vv, zz, csuf, cpre, order, boff,
                                    qu, qw, out, nullptr, nullptr,
                                    BDIM, FDIM, 0, 2);
}

// round 7
// speedup vs baseline: 1.4164x; 1.0279x over previous
#include <cuda_runtime.h>
#include <cuda_bf16.h>
#include <math.h>
#include <cstdint>

#define BDIM 8
#define NDIM 1024
#define DDIM 256
#define HDIM 8
#define FDIM 128
#define MDIM (BDIM * NDIM)   // 8192
#define ALPHA 0.2f

// ---------------- scratch (device globals) ----------------
__device__ float g_h1[HDIM * MDIM * FDIM];            // 33.5 MB (V for layer1)
__device__ float g_h2[MDIM * FDIM];                   // 4 MB (V for layer2)
__device__ __nv_bfloat16 g_xh[MDIM * DDIM];
__device__ __nv_bfloat16 g_xl[MDIM * DDIM];
__device__ __nv_bfloat16 g_w1h[HDIM * FDIM * DDIM];   // W1^T [h][n][k]
__device__ __nv_bfloat16 g_w1l[HDIM * FDIM * DDIM];
__device__ __nv_bfloat16 g_w2h[FDIM * (HDIM * FDIM)]; // W2^T [n][k]
__device__ __nv_bfloat16 g_w2l[FDIM * (HDIM * FDIM)];
__device__ __nv_bfloat16 g_xch[MDIM * HDIM * FDIM];   // xc hi (layer2 A)
__device__ __nv_bfloat16 g_xcl[MDIM * HDIM * FDIM];
__device__ float g_f1a[HDIM * MDIM];
__device__ float g_f2a[HDIM * MDIM];
__device__ float g_f1b[MDIM];
__device__ float g_f2b[MDIM];
__device__ int   g_perm[64 * 1024];
__device__ float g_vv[64 * 1024];
__device__ float g_zz[64 * 1024];
__device__ int   g_order[64 * 1024];
__device__ int   g_boff[64 * 33];
__device__ float g_qu[64 * 1024];
__device__ float g_qw[64 * 1024];
__device__ float g_csuf[64 * 32 * 128];
__device__ float g_cpre[64 * 32 * 128];

__device__ __forceinline__ float lrelu(float x) { return x > 0.f ? x : ALPHA * x; }
__device__ __forceinline__ float elu1(float x)  { return x > 0.f ? x : expm1f(x); }

__device__ __forceinline__ uint32_t smem_to_u32(const void* p) {
    uint32_t a;
    asm("{ .reg .u64 t; cvta.to.shared.u64 t, %1; cvt.u32.u64 %0, t; }"
        : "=r"(a) : "l"(p));
    return a;
}

#define LDSM4(r0, r1, r2, r3, addr) \
    asm volatile("ldmatrix.sync.aligned.m8n8.x4.shared.b16 {%0,%1,%2,%3}, [%4];" \
                 : "=r"(r0), "=r"(r1), "=r"(r2), "=r"(r3) : "r"(addr))

#define MMA16816(c, a, b) \
    asm volatile("mma.sync.aligned.m16n8k16.row.col.f32.bf16.bf16.f32 " \
                 "{%0,%1,%2,%3}, {%4,%5,%6,%7}, {%8,%9}, {%0,%1,%2,%3};" \
                 : "+f"((c)[0]), "+f"((c)[1]), "+f"((c)[2]), "+f"((c)[3]) \
                 : "r"((a)[0]), "r"((a)[1]), "r"((a)[2]), "r"((a)[3]), \
                   "r"((b)[0]), "r"((b)[1]))

// ================= fused conversions =================
// blocks [0, 8192): split x into hi/lo.  blocks [8192, 9216): transpose+split W1.
__global__ void conv1_kernel(const float* __restrict__ x,
                             __nv_bfloat16* __restrict__ xh,
                             __nv_bfloat16* __restrict__ xl,
                             const float* __restrict__ W1,
                             __nv_bfloat16* __restrict__ w1h,
                             __nv_bfloat16* __restrict__ w1l)
{
    int b = blockIdx.x;
    if (b < 8192) {
        int i = b * 256 + threadIdx.x;
        float v = x[i];
        __nv_bfloat16 h = __float2bfloat16(v);
        xh[i] = h;
        xl[i] = __float2bfloat16(v - __bfloat162float(h));
    } else {
        int idx = (b - 8192) * 256 + threadIdx.x;   // over HDIM*DDIM*128
        int h = idx / (DDIM * 128);
        int rem = idx % (DDIM * 128);
        int k = rem >> 7, n = rem & 127;
        float v = W1[idx];
        __nv_bfloat16 hh = __float2bfloat16(v);
        int o = h * DDIM * 128 + n * DDIM + k;
        w1h[o] = hh;
        w1l[o] = __float2bfloat16(v - __bfloat162float(hh));
    }
}

// W2[k][128] -> W2t[n][K] hi/lo, K = 1024
__global__ void trw2_kernel(const float* __restrict__ W,
                            __nv_bfloat16* __restrict__ oh,
                            __nv_bfloat16* __restrict__ ol)
{
    int idx = blockIdx.x * 256 + threadIdx.x;
    int k = idx >> 7, n = idx & 127;
    float v = W[idx];
    __nv_bfloat16 hh = __float2bfloat16(v);
    int o = n * (HDIM * FDIM) + k;
    oh[o] = hh;
    ol[o] = __float2bfloat16(v - __bfloat162float(hh));
}

// ================= bf16x3 HMMA GEMM + fused f1/f2 =================
template<int BM, int WARPS_M, int WARPS_N, int MINB>
__global__ void __launch_bounds__(256, MINB)
mma_gemm(const __nv_bfloat16* __restrict__ Ah, const __nv_bfloat16* __restrict__ Al,
         int K,
         const __nv_bfloat16* __restrict__ Bh_base,
         const __nv_bfloat16* __restrict__ Bl_base,
         const float* __restrict__ avec_base, int aStride,
         float* __restrict__ O_base, long long oHeadStride,
         float* __restrict__ f1g, float* __restrict__ f2g, int fHeadStride)
{
    constexpr int TM = BM / WARPS_M;
    constexpr int TN = 128 / WARPS_N;
    constexpr int MT = TM / 16;
    constexpr int NT = TN / 8;
    constexpr int RSTR = 80;

    __shared__ __align__(16) char smem[(2 * BM + 2 * 128) * RSTR];
    __shared__ float a1s[128], a2s[128];
    __shared__ float sf1[BM], sf2[BM];
    char* sAh = smem;
    char* sAl = smem + BM * RSTR;
    char* sBh = smem + 2 * BM * RSTR;
    char* sBl = smem + (2 * BM + 128) * RSTR;

    const int h = blockIdx.y;
    const __nv_bfloat16* Bh = Bh_base + (size_t)h * 128 * K;
    const __nv_bfloat16* Bl = Bl_base + (size_t)h * 128 * K;
    const float* avec = avec_base + (size_t)h * aStride;
    float* O = O_base + (size_t)h * oHeadStride;
    const int r0 = blockIdx.x * BM;

    const int tid = threadIdx.x, wid = tid >> 5, lane = tid & 31;
    const int warp_m = wid % WARPS_M, warp_n = wid / WARPS_M;
    const int g = lane >> 2, t = lane & 3;

    if (tid < 128) { a1s[tid] = avec[tid]; a2s[tid] = avec[128 + tid]; }
    if (tid < BM) { sf1[tid] = 0.f; sf2[tid] = 0.f; }

    const uint32_t sbase = smem_to_u32(smem);
    const uint32_t aAddr = sbase + (uint32_t)(warp_m * TM + (lane & 15)) * RSTR
                           + (uint32_t)((lane >> 4) * 16);
    const uint32_t bAddr = sbase + (uint32_t)(2 * BM * RSTR)
                           + (uint32_t)((warp_n * TN + (lane & 7) + ((lane & 16) ? 8 : 0)) * RSTR)
                           + (uint32_t)((lane & 8) ? 16 : 0);

    float acc[MT][NT][4] = {};

    for (int k0 = 0; k0 < K; k0 += 32) {
#pragma unroll
        for (int it = 0; it < (BM * 4) / 256; it++) {
            int idx = tid + it * 256;
            int m = idx >> 2, kc = idx & 3;
            int doff = m * RSTR + kc * 16;
            size_t soff = (size_t)(r0 + m) * K + k0 + kc * 8;
            *(uint4*)(sAh + doff) = *(const uint4*)(Ah + soff);
            *(uint4*)(sAl + doff) = *(const uint4*)(Al + soff);
        }
#pragma unroll
        for (int it = 0; it < 2; it++) {
            int idx = tid + it * 256;
            int n = idx >> 2, kc = idx & 3;
            int doff = n * RSTR + kc * 16;
            size_t soff = (size_t)n * K + k0 + kc * 8;
            *(uint4*)(sBh + doff) = *(const uint4*)(Bh + soff);
            *(uint4*)(sBl + doff) = *(const uint4*)(Bl + soff);
        }
        __syncthreads();

#pragma unroll
        for (int s = 0; s < 2; s++) {
            uint32_t bh[NT][2], bl[NT][2];
#pragma unroll
            for (int jj = 0; jj < NT / 2; jj++) {
                uint32_t ad = bAddr + (uint32_t)(jj * 16 * RSTR + s * 32);
                LDSM4(bh[2 * jj][0], bh[2 * jj][1], bh[2 * jj + 1][0], bh[2 * jj + 1][1], ad);
                LDSM4(bl[2 * jj][0], bl[2 * jj][1], bl[2 * jj + 1][0], bl[2 * jj + 1][1],
                      ad + 128 * RSTR);
            }
#pragma unroll
            for (int i = 0; i < MT; i++) {
                uint32_t a_h[4], a_l[4];
                uint32_t ad = aAddr + (uint32_t)(i * 16 * RSTR + s * 32);
                LDSM4(a_h[0], a_h[1], a_h[2], a_h[3], ad);
                LDSM4(a_l[0], a_l[1], a_l[2], a_l[3], ad + BM * RSTR);
#pragma unroll
                for (int j = 0; j < NT; j++) {
                    MMA16816(acc[i][j], a_h, bh[j]);
                    MMA16816(acc[i][j], a_h, bl[j]);
                    MMA16816(acc[i][j], a_l, bh[j]);
                }
            }
        }
        __syncthreads();
    }

    // store O + fused f1/f2 partials (register-lean: one i at a time)
#pragma unroll
    for (int i = 0; i < MT; i++) {
        float p1a = 0.f, p1b = 0.f, p2a = 0.f, p2b = 0.f;
#pragma unroll
        for (int j = 0; j < NT; j++) {
            int row = r0 + warp_m * TM + i * 16 + g;
            int col = warp_n * TN + j * 8 + 2 * t;
            *(float2*)&O[(size_t)row * FDIM + col] =
                make_float2(acc[i][j][0], acc[i][j][1]);
            *(float2*)&O[(size_t)(row + 8) * FDIM + col] =
                make_float2(acc[i][j][2], acc[i][j][3]);
            float a10 = a1s[col], a11 = a1s[col + 1];
            float a20 = a2s[col], a21 = a2s[col + 1];
            p1a += acc[i][j][0] * a10 + acc[i][j][1] * a11;
            p2a += acc[i][j][0] * a20 + acc[i][j][1] * a21;
            p1b += acc[i][j][2] * a10 + acc[i][j][3] * a11;
            p2b += acc[i][j][2] * a20 + acc[i][j][3] * a21;
        }
#pragma unroll
        for (int o = 1; o <= 2; o <<= 1) {
            p1a += __shfl_xor_sync(0xffffffffu, p1a, o);
            p1b += __shfl_xor_sync(0xffffffffu, p1b, o);
            p2a += __shfl_xor_sync(0xffffffffu, p2a, o);
            p2b += __shfl_xor_sync(0xffffffffu, p2b, o);
        }
        if (t == 0) {
            int rloc = warp_m * TM + i * 16 + g;
            atomicAdd(&sf1[rloc], p1a);
            atomicAdd(&sf2[rloc], p2a);
            atomicAdd(&sf1[rloc + 8], p1b);
            atomicAdd(&sf2[rloc + 8], p2b);
        }
    }
    __syncthreads();
    if (tid < BM) {
        f1g[(size_t)h * fHeadStride + r0 + tid] = sf1[tid];
        f2g[(size_t)h * fHeadStride + r0 + tid] = sf2[tid];
    }
}

// ---------------- prep: warp-bitonic sort + warp scans + buckets -------------
__global__ void prep_kernel(const float* __restrict__ f1,
                            const float* __restrict__ f2,
                            int* __restrict__ perm,
                            float* __restrict__ vv, float* __restrict__ zz,
                            int* __restrict__ order, int* __restrict__ boff,
                            float* __restrict__ qu, float* __restrict__ qw)
{
    __shared__ float val[1024];
    __shared__ int   idx[1024];
    __shared__ float prez_s[1025], sufv_s[1025];
    __shared__ float wz[32], wv[32];
    __shared__ float totv_s;
    __shared__ int bcnt[32], boffs[33], bpos[32];

    const int hb = blockIdx.x, tid = threadIdx.x;   // 1024 threads
    const int lane = tid & 31;

    float v = f2[hb * 1024 + tid];
    int ix = tid;
    if (tid < 32) bcnt[tid] = 0;

    // phase 1: k = 2..32 entirely in registers (shfl)
#pragma unroll
    for (int k = 2; k <= 32; k <<= 1) {
        const bool up = ((tid & k) == 0);
#pragma unroll
        for (int j = k >> 1; j; j >>= 1) {
            float pv = __shfl_xor_sync(0xffffffffu, v, j);
            int   pi = __shfl_xor_sync(0xffffffffu, ix, j);
            bool lower = ((lane & j) == 0);
            bool gt = (v > pv) || (v == pv && ix > pi);
            bool take = (gt != lower) != up;   // gt ^ lower ^ up
            if (take) { v = pv; ix = pi; }
        }
    }
    val[tid] = v; idx[tid] = ix;
    __syncthreads();

    // phase 2: k = 64..1024; j>=32 via smem, j<32 via shfl
#pragma unroll
    for (int k = 64; k <= 1024; k <<= 1) {
        const bool up = ((tid & k) == 0);
        for (int j = k >> 1; j >= 32; j >>= 1) {
            int t2 = tid ^ j;
            if (t2 > tid) {
                float a = val[tid], b2 = val[t2];
                int ia = idx[tid], ib = idx[t2];
                bool gt = (a > b2) || (a == b2 && ia > ib);
                if (gt == up) {
                    val[tid] = b2; val[t2] = a;
                    idx[tid] = ib; idx[t2] = ia;
                }
            }
            __syncthreads();
        }
        v = val[tid]; ix = idx[tid];
#pragma unroll
        for (int j = 16; j; j >>= 1) {
            float pv = __shfl_xor_sync(0xffffffffu, v, j);
            int   pi = __shfl_xor_sync(0xffffffffu, ix, j);
            bool lower = ((lane & j) == 0);
            bool gt = (v > pv) || (v == pv && ix > pi);
            bool take = (gt != lower) != up;
            if (take) { v = pv; ix = pi; }
        }
        val[tid] = v; idx[tid] = ix;
        __syncthreads();
    }

    const float M = val[1023];
    const float myv = val[tid];
    const float vex = __expf(myv - M);
    const float zex = __expf(0.2f * (myv - M));
    vv[hb * 1024 + tid] = vex;
    zz[hb * 1024 + tid] = zex;
    perm[hb * 1024 + tid] = idx[tid];

    // dual warp scans (inclusive) of zex (prefix) and vex (for suffix)
    float sz = zex, sv = vex;
#pragma unroll
    for (int o = 1; o < 32; o <<= 1) {
        float tz = __shfl_up_sync(0xffffffffu, sz, o);
        float tv = __shfl_up_sync(0xffffffffu, sv, o);
        if (lane >= o) { sz += tz; sv += tv; }
    }
    if (lane == 31) { wz[tid >> 5] = sz; wv[tid >> 5] = sv; }
    __syncthreads();
    if (tid < 32) {
        float az = wz[tid], av = wv[tid];
        float iz = az, iv = av;
#pragma unroll
        for (int o = 1; o < 32; o <<= 1) {
            float tz = __shfl_up_sync(0xffffffffu, iz, o);
            float tv = __shfl_up_sync(0xffffffffu, iv, o);
            if (tid >= o) { iz += tz; iv += tv; }
        }
        wz[tid] = iz - az;   // exclusive
        wv[tid] = iv - av;
        if (tid == 31) totv_s = iv;
    }
    __syncthreads();
    float incz = sz + wz[tid >> 5];
    float incv = sv + wv[tid >> 5];
    prez_s[tid + 1] = incz;
    sufv_s[tid] = totv_s - (incv - vex);
    if (tid == 0) { prez_s[0] = 0.f; sufv_s[1024] = 0.f; }
    __syncthreads();

    // per-query: threshold + softmax params
    float f1v = f1[hb * 1024 + tid];
    float target = -f1v;
    int lo = 0, hi = 1024;
    while (lo < hi) {
        int mid = (lo + hi) >> 1;
        if (val[mid] <= target) lo = mid + 1; else hi = mid;
    }
    const int tt = lo;
    float su = f1v + M;
    float m = lrelu(su);
    float u = __expf(su - m);
    float w = __expf(0.2f * su - m);
    float d = u * sufv_s[tt] + w * prez_s[tt];
    float invd = 1.f / d;
    qu[hb * 1024 + tid] = u * invd;
    qw[hb * 1024 + tid] = w * invd;

    int c = tt >> 5; if (c > 31) c = 31;
    atomicAdd(&bcnt[c], 1);
    __syncthreads();
    if (tid == 0) {
        int s = 0;
        for (int q = 0; q < 32; q++) { boffs[q] = s; bpos[q] = s; s += bcnt[q]; }
        boffs[32] = s;
    }
    __syncthreads();
    int pos = atomicAdd(&bpos[c], 1);
    order[hb * 1024 + pos] = tid | (tt << 12);
    if (tid < 33) boff[hb * 33 + tid] = boffs[tid];
}

// ---------------- chunk raw weighted sums ------------------------------------
__global__ void chunk_kernel(const float* __restrict__ V,
                             const int* __restrict__ perm,
                             const float* __restrict__ vv,
                             const float* __restrict__ zz,
                             float* __restrict__ csuf, float* __restrict__ cpre)
{
    __shared__ int ps[32];
    __shared__ float vs[32], zs[32];
    const int c = blockIdx.x & 31, hb = blockIdx.x >> 5;
    const int f = threadIdx.x;   // 128

    if (f < 32) {
        int g = hb * 1024 + c * 32 + f;
        ps[f] = perm[g]; vs[f] = vv[g]; zs[f] = zz[g];
    }
    __syncthreads();

    const float* Vh = V + (size_t)hb * NDIM * FDIM;
    float sv = 0.f, sz = 0.f;
#pragma unroll 8
    for (int r = 0; r < 32; r++) {
        float x = Vh[(size_t)ps[r] * FDIM + f];
        sv += vs[r] * x;
        sz += zs[r] * x;
    }
    csuf[(size_t)(hb * 32 + c) * 128 + f] = sv;
    cpre[(size_t)(hb * 32 + c) * 128 + f] = sz;
}

// ---------------- output: per-chunk boundary finish + elu --------------------
__global__ void outd_kernel(const float* __restrict__ V,
                            const int* __restrict__ perm,
                            const float* __restrict__ vv,
                            const float* __restrict__ zz,
                            const float* __restrict__ csuf,
                            const float* __restrict__ cpre,
                            const int* __restrict__ order,
                            const int* __restrict__ boff,
                            const float* __restrict__ qu,
                            const float* __restrict__ qw,
                            float* __restrict__ out,
                            __nv_bfloat16* __restrict__ outH,
                            __nv_bfloat16* __restrict__ outL,
                            int Bdim, int outRowStride, int headColMul, int nElu)
{
    __shared__ __align__(16) float Vb[32 * 128];
    __shared__ float bsuf[128], bpre[128];
    __shared__ float vs[32], zs[32];
    __shared__ int ps[32];

    const int c = blockIdx.x & 31, hb = blockIdx.x >> 5;
    const int h = hb / Bdim, b = hb % Bdim;
    const int tid = threadIdx.x;   // 256

    if (tid < 32) {
        int g = hb * 1024 + c * 32 + tid;
        ps[tid] = perm[g]; vs[tid] = vv[g]; zs[tid] = zz[g];
    }
    __syncthreads();

    const float* Vh = V + (size_t)hb * NDIM * FDIM;
#pragma unroll
    for (int j = 0; j < 16; j++) {
        int e = tid + j * 256;
        int r = e >> 7, f = e & 127;
        Vb[r * 128 + f] = Vh[(size_t)ps[r] * FDIM + f];
    }
    if (tid < 128) {
        float s = 0.f;
        for (int cc = c + 1; cc < 32; cc++) s += csuf[(size_t)(hb * 32 + cc) * 128 + tid];
        bsuf[tid] = s;
    } else {
        int f = tid - 128;
        float s = 0.f;
        for (int cc = 0; cc < c; cc++) s += cpre[(size_t)(hb * 32 + cc) * 128 + f];
        bpre[f] = s;
    }
    __syncthreads();

    const int start = boff[hb * 33 + c], end = boff[hb * 33 + c + 1];
    const int lane = tid & 31, wid = tid >> 5;
    for (int p = start + wid; p < end; p += 8) {
        int e = order[hb * 1024 + p];
        int qi = e & 0xFFF;
        int t  = e >> 12;
        float u = qu[hb * 1024 + qi];
        float w = qw[hb * 1024 + qi];
        const int f0 = lane * 4;
        float4 acc;
        acc.x = u * bsuf[f0 + 0] + w * bpre[f0 + 0];
        acc.y = u * bsuf[f0 + 1] + w * bpre[f0 + 1];
        acc.z = u * bsuf[f0 + 2] + w * bpre[f0 + 2];
        acc.w = u * bsuf[f0 + 3] + w * bpre[f0 + 3];
#pragma unroll 8
        for (int r = 0; r < 32; r++) {
            int gr = c * 32 + r;
            float coef = (gr >= t) ? u * vs[r] : w * zs[r];
            float4 xv = *(const float4*)&Vb[r * 128 + f0];
            acc.x += coef * xv.x;
            acc.y += coef * xv.y;
            acc.z += coef * xv.z;
            acc.w += coef * xv.w;
        }
        float4 o;
        o.x = elu1(acc.x); o.y = elu1(acc.y); o.z = elu1(acc.z); o.w = elu1(acc.w);
        if (nElu == 2) { o.x = elu1(o.x); o.y = elu1(o.y); o.z = elu1(o.z); o.w = elu1(o.w); }
        size_t oidx = ((size_t)(b * NDIM + qi)) * outRowStride + h * headColMul + f0;
        if (outH) {
            float vals[4] = {o.x, o.y, o.z, o.w};
#pragma unroll
            for (int q = 0; q < 4; q++) {
                __nv_bfloat16 hi = __float2bfloat16(vals[q]);
                outH[oidx + q] = hi;
                outL[oidx + q] = __float2bfloat16(vals[q] - __bfloat162float(hi));
            }
        } else {
            *(float4*)&out[oidx] = o;
        }
    }
}

// -----------------------------------------------------------------------------
extern "C" void kernel_launch(void* const* d_in, const int* in_sizes, int n_in,
                              void* d_out, int out_size)
{
    const float* x       = (const float*)d_in[0];
    // d_in[1] = adj : discarded by the reference math
    const float* W_heads = (const float*)d_in[2];
    const float* a_heads = (const float*)d_in[3];
    const float* W_out   = (const float*)d_in[4];
    const float* a_out   = (const float*)d_in[5];
    float* out = (float*)d_out;

    float *h1, *h2, *f1a, *f2a, *f1b, *f2b;
    float *vv, *zz, *qu, *qw, *csuf, *cpre;
    int *perm, *order, *boff;
    __nv_bfloat16 *xh, *xl, *w1h, *w1l, *w2h, *w2l, *xch, *xcl;
    cudaGetSymbolAddress((void**)&h1,    g_h1);
    cudaGetSymbolAddress((void**)&h2,    g_h2);
    cudaGetSymbolAddress((void**)&f1a,   g_f1a);
    cudaGetSymbolAddress((void**)&f2a,   g_f2a);
    cudaGetSymbolAddress((void**)&f1b,   g_f1b);
    cudaGetSymbolAddress((void**)&f2b,   g_f2b);
    cudaGetSymbolAddress((void**)&perm,  g_perm);
    cudaGetSymbolAddress((void**)&vv,    g_vv);
    cudaGetSymbolAddress((void**)&zz,    g_zz);
    cudaGetSymbolAddress((void**)&order, g_order);
    cudaGetSymbolAddress((void**)&boff,  g_boff);
    cudaGetSymbolAddress((void**)&qu,    g_qu);
    cudaGetSymbolAddress((void**)&qw,    g_qw);
    cudaGetSymbolAddress((void**)&csuf,  g_csuf);
    cudaGetSymbolAddress((void**)&cpre,  g_cpre);
    cudaGetSymbolAddress((void**)&xh,    g_xh);
    cudaGetSymbolAddress((void**)&xl,    g_xl);
    cudaGetSymbolAddress((void**)&w1h,   g_w1h);
    cudaGetSymbolAddress((void**)&w1l,   g_w1l);
    cudaGetSymbolAddress((void**)&w2h,   g_w2h);
    cudaGetSymbolAddress((void**)&w2l,   g_w2l);
    cudaGetSymbolAddress((void**)&xch,   g_xch);
    cudaGetSymbolAddress((void**)&xcl,   g_xcl);

    // launch 0: fused x-split + W1 transpose-split
    conv1_kernel<<<8192 + 1024, 256>>>(x, xh, xl, W_heads, w1h, w1l);
    // launch 1: W2 transpose-split
    trw2_kernel<<<(FDIM * HDIM * FDIM) / 256, 256>>>(W_out, w2h, w2l);

    // launch 2: layer-1 GEMM + fused f1/f2
    mma_gemm<128, 2, 4, 1><<<dim3(MDIM / 128, HDIM), 256>>>(
        xh, xl, DDIM, w1h, w1l, a_heads, 2 * FDIM,
        h1, (long long)MDIM * FDIM, f1a, f2a, MDIM);
    // launch 3 (PROFILED): prep L1
    prep_kernel<<<HDIM * BDIM, 1024>>>(f1a, f2a, perm, vv, zz, order, boff, qu, qw);
    chunk_kernel<<<HDIM * BDIM * 32, 128>>>(h1, perm, vv, zz, csuf, cpre);
    outd_kernel<<<HDIM * BDIM * 32, 256>>>(h1, perm, vv, zz, csuf, cpre, order, boff,
                                           qu, qw, nullptr, xch, xcl,
                                           BDIM, HDIM * FDIM, FDIM, 1);

    // layer 2
    mma_gemm<64, 1, 8, 2><<<dim3(MDIM / 64, 1), 256>>>(
        xch, xcl, HDIM * FDIM, w2h, w2l, a_out, 0,
        h2, 0, f1b, f2b, 0);
    prep_kernel<<<BDIM, 1024>>>(f1b, f2b, perm, vv, zz, order, boff, qu, qw);
    chunk_kernel<<<BDIM * 32, 128>>>(h2, perm, vv, zz, csuf, cpre);
    outd_kernel<<<BDIM * 32, 256>>>(h2, perm, vv, zz, csuf, cpre, order, boff,
                                    qu, qw, out, nullptr, nullptr,
                                    BDIM, FDIM, 0, 2);
}

// round 8
// speedup vs baseline: 1.4243x; 1.0056x over previous
#include <cuda_runtime.h>
#include <cuda_bf16.h>
#include <math.h>
#include <cstdint>

#define BDIM 8
#define NDIM 1024
#define DDIM 256
#define HDIM 8
#define FDIM 128
#define MDIM (BDIM * NDIM)   // 8192
#define ALPHA 0.2f

// ---------------- scratch (device globals) ----------------
__device__ float g_h1[HDIM * MDIM * FDIM];            // 33.5 MB (V for layer1)
__device__ float g_h2[MDIM * FDIM];                   // 4 MB (V for layer2)
__device__ __nv_bfloat16 g_xh[MDIM * DDIM];
__device__ __nv_bfloat16 g_xl[MDIM * DDIM];
__device__ __nv_bfloat16 g_w1h[HDIM * FDIM * DDIM];   // W1^T [h][n][k]
__device__ __nv_bfloat16 g_w1l[HDIM * FDIM * DDIM];
__device__ __nv_bfloat16 g_w2h[FDIM * (HDIM * FDIM)]; // W2^T [n][k]
__device__ __nv_bfloat16 g_w2l[FDIM * (HDIM * FDIM)];
__device__ __nv_bfloat16 g_xch[MDIM * HDIM * FDIM];   // xc hi (layer2 A)
__device__ __nv_bfloat16 g_xcl[MDIM * HDIM * FDIM];
__device__ float g_f1a[HDIM * MDIM];
__device__ float g_f2a[HDIM * MDIM];
__device__ float g_f1b[MDIM];
__device__ float g_f2b[MDIM];
__device__ int   g_perm[64 * 1024];
__device__ float g_vv[64 * 1024];
__device__ float g_zz[64 * 1024];
__device__ int   g_order[64 * 1024];
__device__ int   g_boff[64 * 33];
__device__ float g_qu[64 * 1024];
__device__ float g_qw[64 * 1024];
__device__ float g_csuf[64 * 32 * 128];
__device__ float g_cpre[64 * 32 * 128];

__device__ __forceinline__ float lrelu(float x) { return x > 0.f ? x : ALPHA * x; }
__device__ __forceinline__ float elu1(float x)  { return x > 0.f ? x : expm1f(x); }

__device__ __forceinline__ uint32_t smem_to_u32(const void* p) {
    uint32_t a;
    asm("{ .reg .u64 t; cvta.to.shared.u64 t, %1; cvt.u32.u64 %0, t; }"
        : "=r"(a) : "l"(p));
    return a;
}
__device__ __forceinline__ uint32_t pack_bf2(float a, float b) {
    __nv_bfloat162 t = __floats2bfloat162_rn(a, b);
    return *(uint32_t*)&t;
}

#define LDSM4(r0, r1, r2, r3, addr) \
    asm volatile("ldmatrix.sync.aligned.m8n8.x4.shared.b16 {%0,%1,%2,%3}, [%4];" \
                 : "=r"(r0), "=r"(r1), "=r"(r2), "=r"(r3) : "r"(addr))

#define MMA16816(c, a, b) \
    asm volatile("mma.sync.aligned.m16n8k16.row.col.f32.bf16.bf16.f32 " \
                 "{%0,%1,%2,%3}, {%4,%5,%6,%7}, {%8,%9}, {%0,%1,%2,%3};" \
                 : "+f"((c)[0]), "+f"((c)[1]), "+f"((c)[2]), "+f"((c)[3]) \
                 : "r"((a)[0]), "r"((a)[1]), "r"((a)[2]), "r"((a)[3]), \
                   "r"((b)[0]), "r"((b)[1]))

#define CP_A16(d, s) \
    asm volatile("cp.async.cg.shared.global [%0], [%1], 16;" :: "r"(d), "l"(s))
#define CP_COMMIT() asm volatile("cp.async.commit_group;" ::: "memory")
#define CP_WAIT0()  asm volatile("cp.async.wait_group 0;" ::: "memory")
#define CP_WAIT1()  asm volatile("cp.async.wait_group 1;" ::: "memory")

// ================= all conversions in one kernel =================
__global__ void conv_all(const float* __restrict__ x,
                         __nv_bfloat16* __restrict__ xh,
                         __nv_bfloat16* __restrict__ xl,
                         const float* __restrict__ W1,
                         __nv_bfloat16* __restrict__ w1h,
                         __nv_bfloat16* __restrict__ w1l,
                         const float* __restrict__ W2,
                         __nv_bfloat16* __restrict__ w2h,
                         __nv_bfloat16* __restrict__ w2l)
{
    int b = blockIdx.x;
    if (b < 8192) {
        int i = b * 256 + threadIdx.x;
        float v = x[i];
        __nv_bfloat16 h = __float2bfloat16(v);
        xh[i] = h;
        xl[i] = __float2bfloat16(v - __bfloat162float(h));
    } else if (b < 8192 + 1024) {
        int idx = (b - 8192) * 256 + threadIdx.x;   // HDIM*DDIM*128
        int h = idx / (DDIM * 128);
        int rem = idx % (DDIM * 128);
        int k = rem >> 7, n = rem & 127;
        float v = W1[idx];
        __nv_bfloat16 hh = __float2bfloat16(v);
        int o = h * DDIM * 128 + n * DDIM + k;
        w1h[o] = hh;
        w1l[o] = __float2bfloat16(v - __bfloat162float(hh));
    } else {
        int idx = (b - 9216) * 256 + threadIdx.x;   // 1024*128
        int k = idx >> 7, n = idx & 127;
        float v = W2[idx];
        __nv_bfloat16 hh = __float2bfloat16(v);
        int o = n * (HDIM * FDIM) + k;
        w2h[o] = hh;
        w2l[o] = __float2bfloat16(v - __bfloat162float(hh));
    }
}

// ================= bf16x3 HMMA GEMM, cp.async double-buffered ================
template<int BM, int WARPS_M, int WARPS_N>
__global__ void __launch_bounds__(256, 1)
mma_gemm(const __nv_bfloat16* __restrict__ Ah, const __nv_bfloat16* __restrict__ Al,
         int K,
         const __nv_bfloat16* __restrict__ Bh_base,
         const __nv_bfloat16* __restrict__ Bl_base,
         const float* __restrict__ avec_base, int aStride,
         float* __restrict__ O_base, long long oHeadStride,
         float* __restrict__ f1g, float* __restrict__ f2g, int fHeadStride)
{
    constexpr int TM = BM / WARPS_M;
    constexpr int TN = 128 / WARPS_N;
    constexpr int MT = TM / 16;
    constexpr int NT = TN / 8;
    constexpr int RSTR = 80;
    constexpr int STAGE = (2 * BM + 256) * RSTR;

    extern __shared__ __align__(16) char dsm[];
    __shared__ float a1s[128], a2s[128];
    __shared__ float sf1[BM], sf2[BM];

    const int h = blockIdx.y;
    const __nv_bfloat16* Bh = Bh_base + (size_t)h * 128 * K;
    const __nv_bfloat16* Bl = Bl_base + (size_t)h * 128 * K;
    const float* avec = avec_base + (size_t)h * aStride;
    float* O = O_base + (size_t)h * oHeadStride;
    const int r0 = blockIdx.x * BM;

    const int tid = threadIdx.x, wid = tid >> 5, lane = tid & 31;
    const int warp_m = wid % WARPS_M, warp_n = wid / WARPS_M;
    const int g = lane >> 2, t = lane & 3;

    if (tid < 128) { a1s[tid] = avec[tid]; a2s[tid] = avec[128 + tid]; }
    if (tid < BM) { sf1[tid] = 0.f; sf2[tid] = 0.f; }

    const uint32_t sbase = smem_to_u32(dsm);
    const uint32_t aOff = (uint32_t)((warp_m * TM + (lane & 15)) * RSTR
                                     + (lane >> 4) * 16);
    const uint32_t bOff = (uint32_t)(2 * BM * RSTR
                           + (warp_n * TN + (lane & 7) + ((lane & 16) ? 8 : 0)) * RSTR
                           + ((lane & 8) ? 16 : 0));

    auto load_stage = [&](int s, int k0) {
        uint32_t st = sbase + (uint32_t)(s * STAGE);
#pragma unroll
        for (int it = 0; it < (BM * 4) / 256; it++) {
            int idx = tid + it * 256;
            int m = idx >> 2, kc = idx & 3;
            uint32_t doff = (uint32_t)(m * RSTR + kc * 16);
            size_t soff = (size_t)(r0 + m) * K + k0 + kc * 8;
            CP_A16(st + doff, Ah + soff);
            CP_A16(st + BM * RSTR + doff, Al + soff);
        }
#pragma unroll
        for (int it = 0; it < 2; it++) {
            int idx = tid + it * 256;
            int n = idx >> 2, kc = idx & 3;
            uint32_t doff = (uint32_t)(n * RSTR + kc * 16);
            size_t soff = (size_t)n * K + k0 + kc * 8;
            CP_A16(st + 2 * BM * RSTR + doff, Bh + soff);
            CP_A16(st + (2 * BM + 128) * RSTR + doff, Bl + soff);
        }
    };

    float acc[MT][NT][4] = {};

    const int NIT = K / 32;
    load_stage(0, 0);
    CP_COMMIT();
    for (int i = 0; i < NIT; i++) {
        if (i + 1 < NIT) {
            load_stage((i + 1) & 1, (i + 1) * 32);
            CP_COMMIT();
            CP_WAIT1();
        } else {
            CP_WAIT0();
        }
        __syncthreads();

        const uint32_t stoff = (uint32_t)((i & 1) * STAGE);
        const uint32_t aAddr = sbase + stoff + aOff;
        const uint32_t bAddr = sbase + stoff + bOff;
#pragma unroll
        for (int s = 0; s < 2; s++) {
            uint32_t bh[NT][2], bl[NT][2];
#pragma unroll
            for (int jj = 0; jj < NT / 2; jj++) {
                uint32_t ad = bAddr + (uint32_t)(jj * 16 * RSTR + s * 32);
                LDSM4(bh[2 * jj][0], bh[2 * jj][1], bh[2 * jj + 1][0], bh[2 * jj + 1][1], ad);
                LDSM4(bl[2 * jj][0], bl[2 * jj][1], bl[2 * jj + 1][0], bl[2 * jj + 1][1],
                      ad + 128 * RSTR);
            }
#pragma unroll
            for (int ii = 0; ii < MT; ii++) {
                uint32_t a_h[4], a_l[4];
                uint32_t ad = aAddr + (uint32_t)(ii * 16 * RSTR + s * 32);
                LDSM4(a_h[0], a_h[1], a_h[2], a_h[3], ad);
                LDSM4(a_l[0], a_l[1], a_l[2], a_l[3], ad + BM * RSTR);
#pragma unroll
                for (int j = 0; j < NT; j++) {
                    MMA16816(acc[ii][j], a_h, bh[j]);
                    MMA16816(acc[ii][j], a_h, bl[j]);
                    MMA16816(acc[ii][j], a_l, bh[j]);
                }
            }
        }
        __syncthreads();
    }

    // store O + fused f1/f2 partials
#pragma unroll
    for (int i = 0; i < MT; i++) {
        float p1a = 0.f, p1b = 0.f, p2a = 0.f, p2b = 0.f;
#pragma unroll
        for (int j = 0; j < NT; j++) {
            int row = r0 + warp_m * TM + i * 16 + g;
            int col = warp_n * TN + j * 8 + 2 * t;
            *(float2*)&O[(size_t)row * FDIM + col] =
                make_float2(acc[i][j][0], acc[i][j][1]);
            *(float2*)&O[(size_t)(row + 8) * FDIM + col] =
                make_float2(acc[i][j][2], acc[i][j][3]);
            float a10 = a1s[col], a11 = a1s[col + 1];
            float a20 = a2s[col], a21 = a2s[col + 1];
            p1a += acc[i][j][0] * a10 + acc[i][j][1] * a11;
            p2a += acc[i][j][0] * a20 + acc[i][j][1] * a21;
            p1b += acc[i][j][2] * a10 + acc[i][j][3] * a11;
            p2b += acc[i][j][2] * a20 + acc[i][j][3] * a21;
        }
#pragma unroll
        for (int o = 1; o <= 2; o <<= 1) {
            p1a += __shfl_xor_sync(0xffffffffu, p1a, o);
            p1b += __shfl_xor_sync(0xffffffffu, p1b, o);
            p2a += __shfl_xor_sync(0xffffffffu, p2a, o);
            p2b += __shfl_xor_sync(0xffffffffu, p2b, o);
        }
        if (t == 0) {
            int rloc = warp_m * TM + i * 16 + g;
            atomicAdd(&sf1[rloc], p1a);
            atomicAdd(&sf2[rloc], p2a);
            atomicAdd(&sf1[rloc + 8], p1b);
            atomicAdd(&sf2[rloc + 8], p2b);
        }
    }
    __syncthreads();
    if (tid < BM) {
        f1g[(size_t)h * fHeadStride + r0 + tid] = sf1[tid];
        f2g[(size_t)h * fHeadStride + r0 + tid] = sf2[tid];
    }
}

// ---------------- prep + chunk fused: sort, scans, queries, chunk sums ------
__global__ void prepchunk_kernel(const float* __restrict__ f1,
                                 const float* __restrict__ f2,
                                 const float* __restrict__ V,
                                 int* __restrict__ perm,
                                 float* __restrict__ vv, float* __restrict__ zz,
                                 int* __restrict__ order, int* __restrict__ boff,
                                 float* __restrict__ qu, float* __restrict__ qw,
                                 float* __restrict__ csuf, float* __restrict__ cpre)
{
    __shared__ float val[1024];
    __shared__ int   idx[1024];
    __shared__ float prez_s[1025], sufv_s[1025];
    __shared__ float wz[32], wv[32];
    __shared__ float totv_s;
    __shared__ int bcnt[32], boffs[33], bpos[32];

    const int hb = blockIdx.x, tid = threadIdx.x;   // 1024 threads
    const int lane = tid & 31;

    float v = f2[hb * 1024 + tid];
    int ix = tid;
    if (tid < 32) bcnt[tid] = 0;

    // bitonic: k = 2..32 in registers
#pragma unroll
    for (int k = 2; k <= 32; k <<= 1) {
        const bool up = ((tid & k) == 0);
#pragma unroll
        for (int j = k >> 1; j; j >>= 1) {
            float pv = __shfl_xor_sync(0xffffffffu, v, j);
            int   pi = __shfl_xor_sync(0xffffffffu, ix, j);
            bool lower = ((lane & j) == 0);
            bool gt = (v > pv) || (v == pv && ix > pi);
            bool take = (gt != lower) != up;
            if (take) { v = pv; ix = pi; }
        }
    }
    val[tid] = v; idx[tid] = ix;
    __syncthreads();

    // k = 64..1024: j>=32 via smem, j<32 via shfl
#pragma unroll
    for (int k = 64; k <= 1024; k <<= 1) {
        const bool up = ((tid & k) == 0);
        for (int j = k >> 1; j >= 32; j >>= 1) {
            int t2 = tid ^ j;
            if (t2 > tid) {
                float a = val[tid], b2 = val[t2];
                int ia = idx[tid], ib = idx[t2];
                bool gt = (a > b2) || (a == b2 && ia > ib);
                if (gt == up) {
                    val[tid] = b2; val[t2] = a;
                    idx[tid] = ib; idx[t2] = ia;
                }
            }
            __syncthreads();
        }
        v = val[tid]; ix = idx[tid];
#pragma unroll
        for (int j = 16; j; j >>= 1) {
            float pv = __shfl_xor_sync(0xffffffffu, v, j);
            int   pi = __shfl_xor_sync(0xffffffffu, ix, j);
            bool lower = ((lane & j) == 0);
            bool gt = (v > pv) || (v == pv && ix > pi);
            bool take = (gt != lower) != up;
            if (take) { v = pv; ix = pi; }
        }
        val[tid] = v; idx[tid] = ix;
        __syncthreads();
    }

    const float M = val[1023];
    const float myv = val[tid];
    const float vex = __expf(myv - M);
    const float zex = __expf(0.2f * (myv - M));
    vv[hb * 1024 + tid] = vex;
    zz[hb * 1024 + tid] = zex;
    perm[hb * 1024 + tid] = idx[tid];

    // dual warp scans
    float sz = zex, sv = vex;
#pragma unroll
    for (int o = 1; o < 32; o <<= 1) {
        float tz = __shfl_up_sync(0xffffffffu, sz, o);
        float tv = __shfl_up_sync(0xffffffffu, sv, o);
        if (lane >= o) { sz += tz; sv += tv; }
    }
    if (lane == 31) { wz[tid >> 5] = sz; wv[tid >> 5] = sv; }
    __syncthreads();
    if (tid < 32) {
        float az = wz[tid], av = wv[tid];
        float iz = az, iv = av;
#pragma unroll
        for (int o = 1; o < 32; o <<= 1) {
            float tz = __shfl_up_sync(0xffffffffu, iz, o);
            float tv = __shfl_up_sync(0xffffffffu, iv, o);
            if (tid >= o) { iz += tz; iv += tv; }
        }
        wz[tid] = iz - az;
        wv[tid] = iv - av;
        if (tid == 31) totv_s = iv;
    }
    __syncthreads();
    float incz = sz + wz[tid >> 5];
    float incv = sv + wv[tid >> 5];
    prez_s[tid + 1] = incz;
    sufv_s[tid] = totv_s - (incv - vex);
    if (tid == 0) { prez_s[0] = 0.f; sufv_s[1024] = 0.f; }
    __syncthreads();

    // queries
    float f1v = f1[hb * 1024 + tid];
    float target = -f1v;
    int lo = 0, hi = 1024;
    while (lo < hi) {
        int mid = (lo + hi) >> 1;
        if (val[mid] <= target) lo = mid + 1; else hi = mid;
    }
    const int tt = lo;
    float su = f1v + M;
    float m = lrelu(su);
    float u = __expf(su - m);
    float w = __expf(0.2f * su - m);
    float d = u * sufv_s[tt] + w * prez_s[tt];
    float invd = 1.f / d;
    qu[hb * 1024 + tid] = u * invd;
    qw[hb * 1024 + tid] = w * invd;

    int c = tt >> 5; if (c > 31) c = 31;
    atomicAdd(&bcnt[c], 1);
    __syncthreads();
    if (tid == 0) {
        int s = 0;
        for (int q = 0; q < 32; q++) { boffs[q] = s; bpos[q] = s; s += bcnt[q]; }
        boffs[32] = s;
    }
    __syncthreads();
    int pos = atomicAdd(&bpos[c], 1);
    order[hb * 1024 + pos] = tid | (tt << 12);
    if (tid < 33) boff[hb * 33 + tid] = boffs[tid];

    // ---- fused chunk sums (reuse smem: val <- vex, prez_s <- zex) ----
    __syncthreads();
    val[tid] = vex;
    prez_s[tid] = zex;
    __syncthreads();
    const float* Vh = V + (size_t)hb * NDIM * FDIM;
#pragma unroll
    for (int it = 0; it < 4; it++) {
        int wk = tid + it * 1024;
        int cc = wk >> 7, f = wk & 127;
        float svv = 0.f, szz = 0.f;
#pragma unroll 8
        for (int r = 0; r < 32; r++) {
            int gr = cc * 32 + r;
            float xv = Vh[(size_t)idx[gr] * FDIM + f];
            svv += val[gr] * xv;
            szz += prez_s[gr] * xv;
        }
        csuf[(size_t)(hb * 32 + cc) * 128 + f] = svv;
        cpre[(size_t)(hb * 32 + cc) * 128 + f] = szz;
    }
}

// ---------------- output: per-chunk boundary finish + elu --------------------
__global__ void outd_kernel(const float* __restrict__ V,
                            const int* __restrict__ perm,
                            const float* __restrict__ vv,
                            const float* __restrict__ zz,
                            const float* __restrict__ csuf,
                            const float* __restrict__ cpre,
                            const int* __restrict__ order,
                            const int* __restrict__ boff,
                            const float* __restrict__ qu,
                            const float* __restrict__ qw,
                            float* __restrict__ out,
                            __nv_bfloat16* __restrict__ outH,
                            __nv_bfloat16* __restrict__ outL,
                            int Bdim, int outRowStride, int headColMul, int nElu)
{
    __shared__ __align__(16) float Vb[32 * 128];
    __shared__ float bsuf[128], bpre[128];
    __shared__ float vs[32], zs[32];
    __shared__ int ps[32];

    const int c = blockIdx.x & 31, hb = blockIdx.x >> 5;
    const int h = hb / Bdim, b = hb % Bdim;
    const int tid = threadIdx.x;   // 256

    if (tid < 32) {
        int g = hb * 1024 + c * 32 + tid;
        ps[tid] = perm[g]; vs[tid] = vv[g]; zs[tid] = zz[g];
    }
    __syncthreads();

    const float* Vh = V + (size_t)hb * NDIM * FDIM;
#pragma unroll
    for (int j = 0; j < 16; j++) {
        int e = tid + j * 256;
        int r = e >> 7, f = e & 127;
        Vb[r * 128 + f] = Vh[(size_t)ps[r] * FDIM + f];
    }
    if (tid < 128) {
        float s = 0.f;
        for (int cc = c + 1; cc < 32; cc++) s += csuf[(size_t)(hb * 32 + cc) * 128 + tid];
        bsuf[tid] = s;
    } else {
        int f = tid - 128;
        float s = 0.f;
        for (int cc = 0; cc < c; cc++) s += cpre[(size_t)(hb * 32 + cc) * 128 + f];
        bpre[f] = s;
    }
    __syncthreads();

    const int start = boff[hb * 33 + c], end = boff[hb * 33 + c + 1];
    const int lane = tid & 31, wid = tid >> 5;
    for (int p = start + wid; p < end; p += 8) {
        int e = order[hb * 1024 + p];
        int qi = e & 0xFFF;
        int t  = e >> 12;
        float u = qu[hb * 1024 + qi];
        float w = qw[hb * 1024 + qi];
        const int f0 = lane * 4;
        float4 acc;
        acc.x = u * bsuf[f0 + 0] + w * bpre[f0 + 0];
        acc.y = u * bsuf[f0 + 1] + w * bpre[f0 + 1];
        acc.z = u * bsuf[f0 + 2] + w * bpre[f0 + 2];
        acc.w = u * bsuf[f0 + 3] + w * bpre[f0 + 3];
#pragma unroll 8
        for (int r = 0; r < 32; r++) {
            int gr = c * 32 + r;
            float coef = (gr >= t) ? u * vs[r] : w * zs[r];
            float4 xv = *(const float4*)&Vb[r * 128 + f0];
            acc.x += coef * xv.x;
            acc.y += coef * xv.y;
            acc.z += coef * xv.z;
            acc.w += coef * xv.w;
        }
        float4 o;
        o.x = elu1(acc.x); o.y = elu1(acc.y); o.z = elu1(acc.z); o.w = elu1(acc.w);
        if (nElu == 2) { o.x = elu1(o.x); o.y = elu1(o.y); o.z = elu1(o.z); o.w = elu1(o.w); }
        size_t oidx = ((size_t)(b * NDIM + qi)) * outRowStride + h * headColMul + f0;
        if (outH) {
            float h0 = __bfloat162float(__float2bfloat16(o.x));
            float h1 = __bfloat162float(__float2bfloat16(o.y));
            float h2 = __bfloat162float(__float2bfloat16(o.z));
            float h3 = __bfloat162float(__float2bfloat16(o.w));
            uint2 hp, lp;
            hp.x = pack_bf2(h0, h1);
            hp.y = pack_bf2(h2, h3);
            lp.x = pack_bf2(o.x - h0, o.y - h1);
            lp.y = pack_bf2(o.z - h2, o.w - h3);
            *(uint2*)&outH[oidx] = hp;
            *(uint2*)&outL[oidx] = lp;
        } else {
            *(float4*)&out[oidx] = o;
        }
    }
}

// -----------------------------------------------------------------------------
extern "C" void kernel_launch(void* const* d_in, const int* in_sizes, int n_in,
                              void* d_out, int out_size)
{
    const float* x       = (const float*)d_in[0];
    // d_in[1] = adj : discarded by the reference math
    const float* W_heads = (const float*)d_in[2];
    const float* a_heads = (const float*)d_in[3];
    const float* W_out   = (const float*)d_in[4];
    const float* a_out   = (const float*)d_in[5];
    float* out = (float*)d_out;

    float *h1, *h2, *f1a, *f2a, *f1b, *f2b;
    float *vv, *zz, *qu, *qw, *csuf, *cpre;
    int *perm, *order, *boff;
    __nv_bfloat16 *xh, *xl, *w1h, *w1l, *w2h, *w2l, *xch, *xcl;
    cudaGetSymbolAddress((void**)&h1,    g_h1);
    cudaGetSymbolAddress((void**)&h2,    g_h2);
    cudaGetSymbolAddress((void**)&f1a,   g_f1a);
    cudaGetSymbolAddress((void**)&f2a,   g_f2a);
    cudaGetSymbolAddress((void**)&f1b,   g_f1b);
    cudaGetSymbolAddress((void**)&f2b,   g_f2b);
    cudaGetSymbolAddress((void**)&perm,  g_perm);
    cudaGetSymbolAddress((void**)&vv,    g_vv);
    cudaGetSymbolAddress((void**)&zz,    g_zz);
    cudaGetSymbolAddress((void**)&order, g_order);
    cudaGetSymbolAddress((void**)&boff,  g_boff);
    cudaGetSymbolAddress((void**)&qu,    g_qu);
    cudaGetSymbolAddress((void**)&qw,    g_qw);
    cudaGetSymbolAddress((void**)&csuf,  g_csuf);
    cudaGetSymbolAddress((void**)&cpre,  g_cpre);
    cudaGetSymbolAddress((void**)&xh,    g_xh);
    cudaGetSymbolAddress((void**)&xl,    g_xl);
    cudaGetSymbolAddress((void**)&w1h,   g_w1h);
    cudaGetSymbolAddress((void**)&w1l,   g_w1l);
    cudaGetSymbolAddress((void**)&w2h,   g_w2h);
    cudaGetSymbolAddress((void**)&w2l,   g_w2l);
    cudaGetSymbolAddress((void**)&xch,   g_xch);
    cudaGetSymbolAddress((void**)&xcl,   g_xcl);

    constexpr int SMEM1 = 2 * (2 * 128 + 256) * 80;   // 81920
    constexpr int SMEM2 = 2 * (2 * 64 + 256) * 80;    // 61440
    static int attr_set = 0;
    if (!attr_set) {
        cudaFuncSetAttribute(mma_gemm<128, 2, 4>,
                             cudaFuncAttributeMaxDynamicSharedMemorySize, SMEM1);
        cudaFuncSetAttribute(mma_gemm<64, 1, 8>,
                             cudaFuncAttributeMaxDynamicSharedMemorySize, SMEM2);
        attr_set = 1;
    }

    // 0: all conversions
    conv_all<<<8192 + 1024 + 512, 256>>>(x, xh, xl, W_heads, w1h, w1l, W_out, w2h, w2l);
    // 1: layer-1 GEMM + fused f1/f2
    mma_gemm<128, 2, 4><<<dim3(MDIM / 128, HDIM), 256, SMEM1>>>(
        xh, xl, DDIM, w1h, w1l, a_heads, 2 * FDIM,
        h1, (long long)MDIM * FDIM, f1a, f2a, MDIM);
    // 2: prep + chunk
    prepchunk_kernel<<<HDIM * BDIM, 1024>>>(f1a, f2a, h1, perm, vv, zz, order, boff,
                                            qu, qw, csuf, cpre);
    // 3 (PROFILED): outd L1
    outd_kernel<<<HDIM * BDIM * 32, 256>>>(h1, perm, vv, zz, csuf, cpre, order, boff,
                                           qu, qw, nullptr, xch, xcl,
                                           BDIM, HDIM * FDIM, FDIM, 1);
    // 4: layer-2 GEMM + fused f1/f2
    mma_gemm<64, 1, 8><<<dim3(MDIM / 64, 1), 256, SMEM2>>>(
        xch, xcl, HDIM * FDIM, w2h, w2l, a_out, 0,
        h2, 0, f1b, f2b, 0);
    // 5: prep + chunk L2
    prepchunk_kernel<<<BDIM, 1024>>>(f1b, f2b, h2, perm, vv, zz, order, boff,
                                     qu, qw, csuf, cpre);
    // 6: outd L2
    outd_kernel<<<BDIM * 32, 256>>>(h2, perm, vv, zz, csuf, cpre, order, boff,
                                    qu, qw, out, nullptr, nullptr,
                                    BDIM, FDIM, 0, 2);
}